// round 10
// baseline (speedup 1.0000x reference)
#include <cuda_runtime.h>
#include <cuda_bf16.h>
#include <math.h>
#include <stdint.h>

// ---------------- problem constants ----------------
constexpr int B_  = 64;
constexpr int N_  = 257;
constexpr int C_  = 768;
constexpr int H_  = 12;
constexpr int D_  = 64;           // C_/H_
constexpr int HID_ = 3072;
constexpr int M_  = B_ * N_;      // 16448 rows
constexpr int C3_ = 3 * C_;       // 2304

constexpr size_t SZ_BNC  = (size_t)M_ * C_;
constexpr size_t SZ_QKV  = (size_t)M_ * C3_;
constexpr size_t SZ_ATT  = (size_t)B_ * H_ * N_ * N_;
constexpr size_t SZ_HID  = (size_t)M_ * HID_;
constexpr size_t SZ_ASUM = (size_t)B_ * N_ * N_;

// ---------------- device scratch (static, no allocs) ----------------
__device__ float g_s   [SZ_BNC];
__device__ float g_t   [SZ_BNC];
__device__ float g_ln  [SZ_BNC];
__device__ float g_q1  [SZ_QKV];
__device__ float g_q2  [SZ_QKV];
__device__ float g_att [SZ_ATT];
__device__ float g_o   [SZ_BNC];
__device__ float g_sc  [SZ_BNC];
__device__ float g_hid [SZ_HID];
__device__ float g_asum[SZ_ASUM];
__device__ float g_heat[(size_t)B_ * N_];

// ================= helpers =================
__device__ __forceinline__ uint32_t smem_u32(const void* p) {
    uint32_t a;
    asm("{ .reg .u64 t; cvta.to.shared.u64 t, %1; cvt.u32.u64 %0, t; }"
        : "=r"(a) : "l"(p));
    return a;
}

#define SW128(o) ((o) ^ (((o) >> 3) & 0x70))

#define LDSM_X4(r0, r1, r2, r3, addr) \
    asm volatile("ldmatrix.sync.aligned.m8n8.x4.shared.b16 {%0,%1,%2,%3}, [%4];" \
        : "=r"(r0), "=r"(r1), "=r"(r2), "=r"(r3) : "r"(addr))

#define MMA16816(d, a, b0, b1) \
    asm volatile("mma.sync.aligned.m16n8k16.row.col.f32.bf16.bf16.f32 " \
        "{%0,%1,%2,%3},{%4,%5,%6,%7},{%8,%9},{%0,%1,%2,%3};" \
        : "+f"((d)[0]), "+f"((d)[1]), "+f"((d)[2]), "+f"((d)[3]) \
        : "r"((a)[0]), "r"((a)[1]), "r"((a)[2]), "r"((a)[3]), "r"(b0), "r"(b1))

#define MMA_TF32(d, a, b0, b1) \
    asm volatile("mma.sync.aligned.m16n8k8.row.col.f32.tf32.tf32.f32 " \
        "{%0,%1,%2,%3},{%4,%5,%6,%7},{%8,%9},{%0,%1,%2,%3};" \
        : "+f"((d)[0]), "+f"((d)[1]), "+f"((d)[2]), "+f"((d)[3]) \
        : "r"((a)[0]), "r"((a)[1]), "r"((a)[2]), "r"((a)[3]), "r"(b0), "r"(b1))

__device__ __forceinline__ uint32_t f2tf(float f) {
    uint32_t r;
    asm("cvt.rna.tf32.f32 %0, %1;" : "=r"(r) : "f"(f));
    return r;
}

// split one fp32 x8 into hi/lo bf16x2 quads
__device__ __forceinline__ void cvt_hilo8(const float* x, uint4& hq, uint4& lq) {
    uint32_t hp[4], lp[4];
#pragma unroll
    for (int i = 0; i < 4; i++) {
        float a = x[2 * i], b = x[2 * i + 1];
        __nv_bfloat162 h2 = __float22bfloat162_rn(make_float2(a, b));
        uint32_t h = *(uint32_t*)&h2;
        hp[i] = h;
        float fa = __uint_as_float(h << 16);
        float fb = __uint_as_float(h & 0xFFFF0000u);
        __nv_bfloat162 l2 = __float22bfloat162_rn(make_float2(a - fa, b - fb));
        lp[i] = *(uint32_t*)&l2;
    }
    hq = make_uint4(hp[0], hp[1], hp[2], hp[3]);
    lq = make_uint4(lp[0], lp[1], lp[2], lp[3]);
}

__device__ __forceinline__ float arf_f(float v) {
    float ep = expf(v), en = expf(-v), en4 = expf(-v - 4.0f);
    float tmp = (ep - en) / (ep + en4);
    return tmp < 0.0f ? 0.0f : tmp;
}

// ================= split-bf16 mma.sync GEMM =================
// ACT: 0 none, 1 gelu(exact erf), 2 arf
// MODE: 0: C=v ; 1: C=v, C2=R+v ; 2: C=R+v
constexpr uint32_t T_AH = 0;
constexpr uint32_t T_AL = 8192;
constexpr uint32_t T_BH = 16384;
constexpr uint32_t T_BL = 24576;
constexpr uint32_t STAGE = 32768;
constexpr int GEMM_SMEM = 65536;

template<int ACT, int MODE>
__global__ __launch_bounds__(256, 1)
void gemm_mma(const float* __restrict__ A, const float* __restrict__ W,
              const float* __restrict__ bias, float* __restrict__ Cmat,
              float* __restrict__ C2, const float* __restrict__ R,
              int M, int Nn, int K) {
    extern __shared__ __align__(1024) char smem[];
    const uint32_t sb = smem_u32(smem);
    const int tid  = threadIdx.x;
    const int wid  = tid >> 5;
    const int lane = tid & 31;
    const int bm   = blockIdx.y * 128;
    const int bn   = blockIdx.x * 128;
    const int wm   = (wid & 3) * 32;
    const int wn   = (wid >> 2) * 64;

    const int lr = tid >> 1;
    const int lk = (tid & 1) * 16;
    const bool aOk = (bm + lr) < M;
    const float* Ap = A + (size_t)(bm + lr) * K + lk;
    const float* Wp = W + (size_t)(bn + lr) * K + lk;

    float acc[2][8][4];
#pragma unroll
    for (int i = 0; i < 2; i++)
#pragma unroll
        for (int j = 0; j < 8; j++)
#pragma unroll
            for (int r = 0; r < 4; r++) acc[i][j][r] = 0.f;

    float ra[16], rb[16];

#pragma unroll
    for (int u = 0; u < 2; ++u) {
        if (aOk) {
            float4 v0 = *(const float4*)(Ap + u * 8);
            float4 v1 = *(const float4*)(Ap + u * 8 + 4);
            ra[u*8+0]=v0.x; ra[u*8+1]=v0.y; ra[u*8+2]=v0.z; ra[u*8+3]=v0.w;
            ra[u*8+4]=v1.x; ra[u*8+5]=v1.y; ra[u*8+6]=v1.z; ra[u*8+7]=v1.w;
        } else {
#pragma unroll
            for (int q = 0; q < 8; q++) ra[u*8+q] = 0.f;
        }
        float4 w0 = *(const float4*)(Wp + u * 8);
        float4 w1 = *(const float4*)(Wp + u * 8 + 4);
        rb[u*8+0]=w0.x; rb[u*8+1]=w0.y; rb[u*8+2]=w0.z; rb[u*8+3]=w0.w;
        rb[u*8+4]=w1.x; rb[u*8+5]=w1.y; rb[u*8+6]=w1.z; rb[u*8+7]=w1.w;
    }
    {
        const uint32_t soff = lr * 64u;
#pragma unroll
        for (int u = 0; u < 2; ++u) {
            uint32_t off = soff + (uint32_t)(lk + u * 8) * 2u;
            uint32_t sw = SW128(off);
            uint4 hq, lq;
            cvt_hilo8(&ra[u * 8], hq, lq);
            *(uint4*)(smem + T_AH + sw) = hq;
            *(uint4*)(smem + T_AL + sw) = lq;
            cvt_hilo8(&rb[u * 8], hq, lq);
            *(uint4*)(smem + T_BH + sw) = hq;
            *(uint4*)(smem + T_BL + sw) = lq;
        }
    }
    __syncthreads();

    const int nit = K >> 5;
    for (int it = 0; it < nit; ++it) {
        if (it + 1 < nit) {
            const int k0 = (it + 1) << 5;
#pragma unroll
            for (int u = 0; u < 2; ++u) {
                if (aOk) {
                    float4 v0 = *(const float4*)(Ap + k0 + u * 8);
                    float4 v1 = *(const float4*)(Ap + k0 + u * 8 + 4);
                    ra[u*8+0]=v0.x; ra[u*8+1]=v0.y; ra[u*8+2]=v0.z; ra[u*8+3]=v0.w;
                    ra[u*8+4]=v1.x; ra[u*8+5]=v1.y; ra[u*8+6]=v1.z; ra[u*8+7]=v1.w;
                } else {
#pragma unroll
                    for (int q = 0; q < 8; q++) ra[u*8+q] = 0.f;
                }
                float4 w0 = *(const float4*)(Wp + k0 + u * 8);
                float4 w1 = *(const float4*)(Wp + k0 + u * 8 + 4);
                rb[u*8+0]=w0.x; rb[u*8+1]=w0.y; rb[u*8+2]=w0.z; rb[u*8+3]=w0.w;
                rb[u*8+4]=w1.x; rb[u*8+5]=w1.y; rb[u*8+6]=w1.z; rb[u*8+7]=w1.w;
            }
        }

        const uint32_t stb = sb + (uint32_t)(it & 1) * STAGE;
#pragma unroll
        for (int ks = 0; ks < 2; ++ks) {
            const int kk = ks * 16;
            uint32_t ah[2][4], al[2][4];
#pragma unroll
            for (int mt = 0; mt < 2; ++mt) {
                uint32_t off = (uint32_t)(wm + mt * 16 + (lane & 15)) * 64u
                             + (uint32_t)(kk + (lane >> 4) * 8) * 2u;
                uint32_t sw = SW128(off);
                LDSM_X4(ah[mt][0], ah[mt][1], ah[mt][2], ah[mt][3], stb + T_AH + sw);
                LDSM_X4(al[mt][0], al[mt][1], al[mt][2], al[mt][3], stb + T_AL + sw);
            }
            // B loads: x4 covers two n-tiles (rows p*16..p*16+15, both k halves)
            uint32_t bh_[8][2], bl_[8][2];
#pragma unroll
            for (int p = 0; p < 4; ++p) {
                uint32_t boff = (uint32_t)(wn + p * 16 + ((lane >> 4) & 1) * 8 + (lane & 7)) * 64u
                              + (uint32_t)(kk + ((lane >> 3) & 1) * 8) * 2u;
                uint32_t bsw = SW128(boff);
                LDSM_X4(bh_[2*p][0], bh_[2*p][1], bh_[2*p+1][0], bh_[2*p+1][1], stb + T_BH + bsw);
                LDSM_X4(bl_[2*p][0], bl_[2*p][1], bl_[2*p+1][0], bl_[2*p+1][1], stb + T_BL + bsw);
            }
            // term-major order: consecutive MMAs hit different accumulators
#pragma unroll
            for (int nt = 0; nt < 8; ++nt) {
                MMA16816(acc[0][nt], ah[0], bh_[nt][0], bh_[nt][1]);
                MMA16816(acc[1][nt], ah[1], bh_[nt][0], bh_[nt][1]);
            }
#pragma unroll
            for (int nt = 0; nt < 8; ++nt) {
                MMA16816(acc[0][nt], ah[0], bl_[nt][0], bl_[nt][1]);
                MMA16816(acc[1][nt], ah[1], bl_[nt][0], bl_[nt][1]);
            }
#pragma unroll
            for (int nt = 0; nt < 8; ++nt) {
                MMA16816(acc[0][nt], al[0], bh_[nt][0], bh_[nt][1]);
                MMA16816(acc[1][nt], al[1], bh_[nt][0], bh_[nt][1]);
            }
        }

        if (it + 1 < nit) {
            const uint32_t base = (uint32_t)((it + 1) & 1) * STAGE;
            const uint32_t soff = lr * 64u;
#pragma unroll
            for (int u = 0; u < 2; ++u) {
                uint32_t off = soff + (uint32_t)(lk + u * 8) * 2u;
                uint32_t sw = SW128(off);
                uint4 hq, lq;
                cvt_hilo8(&ra[u * 8], hq, lq);
                *(uint4*)(smem + base + T_AH + sw) = hq;
                *(uint4*)(smem + base + T_AL + sw) = lq;
                cvt_hilo8(&rb[u * 8], hq, lq);
                *(uint4*)(smem + base + T_BH + sw) = hq;
                *(uint4*)(smem + base + T_BL + sw) = lq;
            }
        }
        __syncthreads();
    }

#pragma unroll
    for (int mt = 0; mt < 2; ++mt) {
#pragma unroll
        for (int half = 0; half < 2; ++half) {
            const int row = bm + wm + mt * 16 + (lane >> 2) + half * 8;
            if (row < M) {
#pragma unroll
                for (int nt = 0; nt < 8; ++nt) {
                    const int col = bn + wn + nt * 8 + (lane & 3) * 2;
                    float v0 = acc[mt][nt][half * 2 + 0];
                    float v1 = acc[mt][nt][half * 2 + 1];
                    if (bias) { v0 += bias[col]; v1 += bias[col + 1]; }
                    if (ACT == 1) {
                        v0 = 0.5f * v0 * (1.0f + erff(v0 * 0.70710678118654752f));
                        v1 = 0.5f * v1 * (1.0f + erff(v1 * 0.70710678118654752f));
                    } else if (ACT == 2) {
                        v0 = arf_f(v0);
                        v1 = arf_f(v1);
                    }
                    const size_t oidx = (size_t)row * Nn + col;
                    if (MODE == 0) {
                        *(float2*)&Cmat[oidx] = make_float2(v0, v1);
                    } else if (MODE == 1) {
                        float2 r = *(const float2*)&R[oidx];
                        *(float2*)&Cmat[oidx] = make_float2(v0, v1);
                        *(float2*)&C2[oidx]   = make_float2(r.x + v0, r.y + v1);
                    } else {
                        float2 r = *(const float2*)&R[oidx];
                        *(float2*)&Cmat[oidx] = make_float2(r.x + v0, r.y + v1);
                    }
                }
            }
        }
    }
}

// ================= fused flash attention (tf32 mma, 512 thr) =================
// One CTA = one (b,h) x 64 q-rows. 16 warps: wq=wid&3 (16 q-rows each),
// wk=wid>>2 splits keys (phase1, 4 chunks) / d (phase3, 4x16).
constexpr int FA_NK  = 264;
constexpr int FA_KST = 68;    // Q/K stride  (68 % 32 == 4  -> conflict-free)
constexpr int FA_SST = 268;   // S/Vt stride (268 % 32 == 12 -> conflict-free)
constexpr int FA_OFF_Q = 0;                          // 64 x 68 (tf32 bits)
constexpr int FA_OFF_K = 64 * FA_KST;                // 264 x 68 (Vt 64 x 268 overlays)
constexpr int FA_OFF_S = FA_OFF_K + FA_NK * FA_KST;  // 64 x 268 (f32)
constexpr int FA_FLOATS = FA_OFF_S + 64 * FA_SST;
constexpr int FATT_SMEM = FA_FLOATS * 4;             // 157,824 B

template<int WRITE_P>
__global__ __launch_bounds__(512, 1)
void k_fattn(const float* __restrict__ qsrc, int qs,
             const float* __restrict__ kvsrc, int kvs, int koff, int voff,
             float* __restrict__ o, float* __restrict__ pout) {
    extern __shared__ __align__(16) float fs[];
    uint32_t* Qs = (uint32_t*)(fs + FA_OFF_Q);
    uint32_t* Ks = (uint32_t*)(fs + FA_OFF_K);
    float*    Ss = fs + FA_OFF_S;

    const int q0 = blockIdx.x * 64;
    const int bh = blockIdx.y;
    const int b = bh / H_, h = bh % H_;
    const int tid = threadIdx.x;
    const int wid = tid >> 5;
    const int lane = tid & 31;
    const int gid = lane >> 2;
    const int tig = lane & 3;
    const int wq = wid & 3;
    const int wk = wid >> 2;        // 0..3
    const int r0 = wq * 16;

    const float* Qg = qsrc + (size_t)b * N_ * qs + h * D_;
    const float* Kg = kvsrc + (size_t)b * N_ * kvs + koff + h * D_;
    const float* Vg = kvsrc + (size_t)b * N_ * kvs + voff + h * D_;

    // ---- load + convert Q (64x64) and K (264x64) to tf32 bits ----
    for (int idx = tid; idx < 64 * 64; idx += 512) {
        int r = idx >> 6, d = idx & 63;
        int q = q0 + r;
        Qs[r * FA_KST + d] = (q < N_) ? f2tf(Qg[(size_t)q * qs + d]) : 0u;
    }
    for (int idx = tid; idx < FA_NK * 64; idx += 512) {
        int r = idx >> 6, d = idx & 63;
        Ks[r * FA_KST + d] = (r < N_) ? f2tf(Kg[(size_t)r * kvs + d]) : 0u;
    }
    __syncthreads();

    // ---- phase 1: S = 0.125 * Q K^T ----
    {
        uint32_t a[8][4];
#pragma unroll
        for (int ks = 0; ks < 8; ++ks) {
            a[ks][0] = Qs[(r0 + gid)     * FA_KST + ks * 8 + tig];
            a[ks][1] = Qs[(r0 + gid + 8) * FA_KST + ks * 8 + tig];
            a[ks][2] = Qs[(r0 + gid)     * FA_KST + ks * 8 + 4 + tig];
            a[ks][3] = Qs[(r0 + gid + 8) * FA_KST + ks * 8 + 4 + tig];
        }
        const int g0 = wk * 8;
        const int g1 = (wk == 3) ? 33 : g0 + 8;
        int g = g0;
        for (; g + 4 <= g1; g += 4) {
            float c[4][4];
#pragma unroll
            for (int j = 0; j < 4; ++j)
#pragma unroll
                for (int r = 0; r < 4; ++r) c[j][r] = 0.f;
#pragma unroll
            for (int ks = 0; ks < 8; ++ks) {
#pragma unroll
                for (int j = 0; j < 4; ++j) {
                    uint32_t b0 = Ks[((g + j) * 8 + gid) * FA_KST + ks * 8 + tig];
                    uint32_t b1 = Ks[((g + j) * 8 + gid) * FA_KST + ks * 8 + 4 + tig];
                    MMA_TF32(c[j], a[ks], b0, b1);
                }
            }
#pragma unroll
            for (int j = 0; j < 4; ++j) {
                Ss[(r0 + gid)     * FA_SST + (g + j) * 8 + tig * 2]     = c[j][0] * 0.125f;
                Ss[(r0 + gid)     * FA_SST + (g + j) * 8 + tig * 2 + 1] = c[j][1] * 0.125f;
                Ss[(r0 + gid + 8) * FA_SST + (g + j) * 8 + tig * 2]     = c[j][2] * 0.125f;
                Ss[(r0 + gid + 8) * FA_SST + (g + j) * 8 + tig * 2 + 1] = c[j][3] * 0.125f;
            }
        }
        for (; g < g1; ++g) {
            float c[4] = {0.f, 0.f, 0.f, 0.f};
#pragma unroll
            for (int ks = 0; ks < 8; ++ks) {
                uint32_t b0 = Ks[(g * 8 + gid) * FA_KST + ks * 8 + tig];
                uint32_t b1 = Ks[(g * 8 + gid) * FA_KST + ks * 8 + 4 + tig];
                MMA_TF32(c, a[ks], b0, b1);
            }
            Ss[(r0 + gid)     * FA_SST + g * 8 + tig * 2]     = c[0] * 0.125f;
            Ss[(r0 + gid)     * FA_SST + g * 8 + tig * 2 + 1] = c[1] * 0.125f;
            Ss[(r0 + gid + 8) * FA_SST + g * 8 + tig * 2]     = c[2] * 0.125f;
            Ss[(r0 + gid + 8) * FA_SST + g * 8 + tig * 2 + 1] = c[3] * 0.125f;
        }
    }
    __syncthreads();

    // ---- phase 2: softmax (4 rows per warp, 16 warps) ----
#pragma unroll 1
    for (int rr = 0; rr < 4; ++rr) {
        const int row = wid * 4 + rr;
        const int q = q0 + row;
        if (q >= N_) continue;
        float* Sr = Ss + (size_t)row * FA_SST;
        float m = -1e30f;
        for (int c = lane; c < N_; c += 32) m = fmaxf(m, Sr[c]);
#pragma unroll
        for (int off = 16; off > 0; off >>= 1)
            m = fmaxf(m, __shfl_xor_sync(0xFFFFFFFF, m, off));
        float sum = 0.f;
        for (int c = lane; c < N_; c += 32) {
            float e = expf(Sr[c] - m);
            Sr[c] = e;
            sum += e;
        }
#pragma unroll
        for (int off = 16; off > 0; off >>= 1)
            sum += __shfl_xor_sync(0xFFFFFFFF, sum, off);
        const float inv = 1.0f / sum;
        for (int c = lane; c < FA_NK; c += 32) {
            float p = (c < N_) ? Sr[c] * inv : 0.f;
            Sr[c] = p;
            if (WRITE_P && c < N_)
                pout[(size_t)bh * N_ * N_ + (size_t)q * N_ + c] = p;
        }
    }
    __syncthreads();

    // ---- phase 3: Vt load (tf32), O = P V (2-term split on P) ----
    uint32_t* Vt = Ks;
    for (int idx = tid; idx < FA_NK * 64; idx += 512) {
        int key = idx >> 6, d = idx & 63;
        Vt[d * FA_SST + key] = (key < N_) ? f2tf(Vg[(size_t)key * kvs + d]) : 0u;
    }
    __syncthreads();

    float oa[2][4];
#pragma unroll
    for (int nt = 0; nt < 2; ++nt)
#pragma unroll
        for (int r = 0; r < 4; ++r) oa[nt][r] = 0.f;

#pragma unroll 1
    for (int ks = 0; ks < 33; ++ks) {
        float p0 = Ss[(r0 + gid)     * FA_SST + ks * 8 + tig];
        float p1 = Ss[(r0 + gid + 8) * FA_SST + ks * 8 + tig];
        float p2 = Ss[(r0 + gid)     * FA_SST + ks * 8 + 4 + tig];
        float p3 = Ss[(r0 + gid + 8) * FA_SST + ks * 8 + 4 + tig];
        uint32_t ah[4], al[4];
        ah[0] = f2tf(p0); al[0] = __float_as_uint(p0 - __uint_as_float(ah[0]));
        ah[1] = f2tf(p1); al[1] = __float_as_uint(p1 - __uint_as_float(ah[1]));
        ah[2] = f2tf(p2); al[2] = __float_as_uint(p2 - __uint_as_float(ah[2]));
        ah[3] = f2tf(p3); al[3] = __float_as_uint(p3 - __uint_as_float(ah[3]));
        uint32_t vb[2][2];
#pragma unroll
        for (int nt = 0; nt < 2; ++nt) {
            vb[nt][0] = Vt[(wk * 16 + nt * 8 + gid) * FA_SST + ks * 8 + tig];
            vb[nt][1] = Vt[(wk * 16 + nt * 8 + gid) * FA_SST + ks * 8 + 4 + tig];
        }
#pragma unroll
        for (int nt = 0; nt < 2; ++nt) MMA_TF32(oa[nt], ah, vb[nt][0], vb[nt][1]);
#pragma unroll
        for (int nt = 0; nt < 2; ++nt) MMA_TF32(oa[nt], al, vb[nt][0], vb[nt][1]);
    }

    // ---- write O ----
    {
        const int q_a = q0 + r0 + gid;
        const int q_b = q_a + 8;
#pragma unroll
        for (int nt = 0; nt < 2; ++nt) {
            const int col = h * D_ + wk * 16 + nt * 8 + tig * 2;
            if (q_a < N_)
                *(float2*)&o[((size_t)(b * N_ + q_a)) * C_ + col] =
                    make_float2(oa[nt][0], oa[nt][1]);
            if (q_b < N_)
                *(float2*)&o[((size_t)(b * N_ + q_b)) * C_ + col] =
                    make_float2(oa[nt][2], oa[nt][3]);
        }
    }
}

// ---------------- elementwise kernels ----------------
__global__ void k_init(const float* __restrict__ src, const float* __restrict__ tgt,
                       const float* __restrict__ pos, float* __restrict__ s,
                       float* __restrict__ t) {
    size_t i = (size_t)blockIdx.x * blockDim.x + threadIdx.x;
    if (i >= SZ_BNC) return;
    size_t nc = i % ((size_t)N_ * C_);
    s[i] = src[i] + pos[nc];
    t[i] = tgt[i];
}

// ---------------- layernorm ----------------
__global__ void k_ln(const float* __restrict__ x, const float* __restrict__ g,
                     const float* __restrict__ b, float* __restrict__ y) {
    int row = blockIdx.x;
    int tid = threadIdx.x;
    const float* xr = x + (size_t)row * C_;
    float s = 0.f, q = 0.f;
    for (int i = tid; i < C_; i += 256) { float v = xr[i]; s += v; q += v * v; }
    __shared__ float rs[256], rq[256];
    rs[tid] = s; rq[tid] = q; __syncthreads();
    for (int o = 128; o > 0; o >>= 1) {
        if (tid < o) { rs[tid] += rs[tid + o]; rq[tid] += rq[tid + o]; }
        __syncthreads();
    }
    float mean = rs[0] * (1.0f / C_);
    float var  = rq[0] * (1.0f / C_) - mean * mean;
    float inv  = rsqrtf(var + 1e-5f);
    float* yr = y + (size_t)row * C_;
    for (int i = tid; i < C_; i += 256)
        yr[i] = (xr[i] - mean) * inv * g[i] + b[i];
}

// ---------------- head sum ----------------
__global__ void k_headsum(const float* __restrict__ attn, float* __restrict__ asum) {
    size_t idx = (size_t)blockIdx.x * 256 + threadIdx.x;
    if (idx >= SZ_ASUM) return;
    size_t b = idx / ((size_t)N_ * N_);
    size_t r = idx % ((size_t)N_ * N_);
    float s = 0.f;
    for (int h = 0; h < H_; h++) s += attn[((size_t)(b * H_ + h)) * N_ * N_ + r];
    asum[idx] = s;
}

// ---------------- heat ----------------
__global__ void k_heat(const float* __restrict__ asum, float* __restrict__ heat) {
    int idx = blockIdx.x * 256 + threadIdx.x;
    if (idx >= B_ * N_) return;
    int b = idx / N_, m = idx % N_;
    const float* p = asum + (size_t)b * N_ * N_ + m;
    float s = 0.f;
    for (int n = 0; n < N_; n++) s += p[(size_t)n * N_];
    heat[idx] = s * (1.0f / N_);
}

// ---------------- tgt output ----------------
__global__ void k_tgt_out(const float* __restrict__ t, const float* __restrict__ saw,
                          const float* __restrict__ heat, float* __restrict__ out) {
    size_t i = (size_t)blockIdx.x * 256 + threadIdx.x;
    if (i >= SZ_BNC) return;
    int row = (int)(i / C_);
    int c   = (int)(i % C_);
    float gate = 1.0f / (1.0f + expf(-heat[row]));
    float tv = t[i];
    out[i] = tv + tv * saw[c] * gate;
}

// ---------------- attm copy ----------------
__global__ void k_attm(const float* __restrict__ asum, float* __restrict__ out) {
    size_t idx = (size_t)blockIdx.x * 256 + threadIdx.x;
    size_t total = (size_t)B_ * 256 * 256;
    if (idx >= total) return;
    size_t b = idx / 65536;
    size_t r = idx % 65536;
    int i = (int)(r >> 8), j = (int)(r & 255);
    out[idx] = asum[(size_t)b * N_ * N_ + (size_t)(i + 1) * N_ + (j + 1)];
}

// ---------------- host orchestration ----------------
static inline dim3 tc_grid(int Nn) { return dim3(Nn / 128, (M_ + 127) / 128); }

extern "C" void kernel_launch(void* const* d_in, const int* in_sizes, int n_in,
                              void* d_out, int out_size) {
    const float* in_src   = (const float*)d_in[0];
    const float* in_tgt   = (const float*)d_in[1];
    const float* sattn_qkv_w  = (const float*)d_in[2];
    const float* sattn_proj_w = (const float*)d_in[3];
    const float* sattn_proj_b = (const float*)d_in[4];
    const float* cattn_qkv_w  = (const float*)d_in[5];
    const float* cattn_proj_w = (const float*)d_in[6];
    const float* cattn_proj_b = (const float*)d_in[7];
    const float* n1g = (const float*)d_in[8];
    const float* n1b = (const float*)d_in[9];
    const float* n2g = (const float*)d_in[10];
    const float* n2b = (const float*)d_in[11];
    const float* fc1_w = (const float*)d_in[12];
    const float* fc1_b = (const float*)d_in[13];
    const float* fc2_w = (const float*)d_in[14];
    const float* fc2_b = (const float*)d_in[15];
    const float* saw   = (const float*)d_in[16];
    const float* pos   = (const float*)d_in[17];

    float *s, *t, *ln, *q1, *q2, *at, *ob, *sc, *hd, *as_, *ht;
    cudaGetSymbolAddress((void**)&s,   g_s);
    cudaGetSymbolAddress((void**)&t,   g_t);
    cudaGetSymbolAddress((void**)&ln,  g_ln);
    cudaGetSymbolAddress((void**)&q1,  g_q1);
    cudaGetSymbolAddress((void**)&q2,  g_q2);
    cudaGetSymbolAddress((void**)&at,  g_att);
    cudaGetSymbolAddress((void**)&ob,  g_o);
    cudaGetSymbolAddress((void**)&sc,  g_sc);
    cudaGetSymbolAddress((void**)&hd,  g_hid);
    cudaGetSymbolAddress((void**)&as_, g_asum);
    cudaGetSymbolAddress((void**)&ht,  g_heat);

    cudaFuncSetAttribute((const void*)gemm_mma<0, 0>,
                         cudaFuncAttributeMaxDynamicSharedMemorySize, GEMM_SMEM);
    cudaFuncSetAttribute((const void*)gemm_mma<0, 1>,
                         cudaFuncAttributeMaxDynamicSharedMemorySize, GEMM_SMEM);
    cudaFuncSetAttribute((const void*)gemm_mma<0, 2>,
                         cudaFuncAttributeMaxDynamicSharedMemorySize, GEMM_SMEM);
    cudaFuncSetAttribute((const void*)gemm_mma<1, 0>,
                         cudaFuncAttributeMaxDynamicSharedMemorySize, GEMM_SMEM);
    cudaFuncSetAttribute((const void*)gemm_mma<2, 1>,
                         cudaFuncAttributeMaxDynamicSharedMemorySize, GEMM_SMEM);
    cudaFuncSetAttribute((const void*)k_fattn<0>,
                         cudaFuncAttributeMaxDynamicSharedMemorySize, FATT_SMEM);
    cudaFuncSetAttribute((const void*)k_fattn<1>,
                         cudaFuncAttributeMaxDynamicSharedMemorySize, FATT_SMEM);

    float* out_src  = (float*)d_out;
    float* out_tgt  = out_src + SZ_BNC;
    float* out_attm = out_tgt + SZ_BNC;

    const int EW = (int)((SZ_BNC + 255) / 256);
    dim3 fa_grid((N_ + 63) / 64, B_ * H_);

    // ---- src = src + pos; t = tgt ----
    k_init<<<EW, 256>>>(in_src, in_tgt, pos, s, t);

    // ---- self attention on src ----
    k_ln<<<M_, 256>>>(s, n1g, n1b, ln);
    gemm_mma<0, 0><<<tc_grid(C3_), 256, GEMM_SMEM>>>(ln, sattn_qkv_w, nullptr, q1,
                                                     nullptr, nullptr, M_, C3_, C_);
    k_fattn<0><<<fa_grid, 512, FATT_SMEM>>>(q1, C3_, q1, C3_, C_, 2 * C_, ob, nullptr);
    // sc = proj(o)+b ; s += sc
    gemm_mma<0, 1><<<tc_grid(C_), 256, GEMM_SMEM>>>(ob, sattn_proj_w, sattn_proj_b, sc,
                                                    s, s, M_, C_, C_);
    k_ln<<<M_, 256>>>(sc, n2g, n2b, ln);
    gemm_mma<1, 0><<<tc_grid(HID_), 256, GEMM_SMEM>>>(ln, fc1_w, fc1_b, hd,
                                                      nullptr, nullptr, M_, HID_, C_);
    // s += fc2(hd)+b
    gemm_mma<0, 2><<<tc_grid(C_), 256, GEMM_SMEM>>>(hd, fc2_w, fc2_b, s,
                                                    nullptr, s, M_, C_, HID_);

    // ---- self attention on tgt ----
    k_ln<<<M_, 256>>>(t, n1g, n1b, ln);
    gemm_mma<0, 0><<<tc_grid(C3_), 256, GEMM_SMEM>>>(ln, sattn_qkv_w, nullptr, q1,
                                                     nullptr, nullptr, M_, C3_, C_);
    k_fattn<0><<<fa_grid, 512, FATT_SMEM>>>(q1, C3_, q1, C3_, C_, 2 * C_, ob, nullptr);
    gemm_mma<0, 1><<<tc_grid(C_), 256, GEMM_SMEM>>>(ob, sattn_proj_w, sattn_proj_b, sc,
                                                    t, t, M_, C_, C_);
    k_ln<<<M_, 256>>>(sc, n2g, n2b, ln);
    gemm_mma<1, 0><<<tc_grid(HID_), 256, GEMM_SMEM>>>(ln, fc1_w, fc1_b, hd,
                                                      nullptr, nullptr, M_, HID_, C_);
    gemm_mma<0, 2><<<tc_grid(C_), 256, GEMM_SMEM>>>(hd, fc2_w, fc2_b, t,
                                                    nullptr, t, M_, C_, HID_);

    // ---- cross attention (Q-only GEMM for src, KV-only for tgt) ----
    k_ln<<<M_, 256>>>(s, n1g, n1b, ln);
    gemm_mma<0, 0><<<tc_grid(C_), 256, GEMM_SMEM>>>(ln, cattn_qkv_w, nullptr, q1,
                                                    nullptr, nullptr, M_, C_, C_);
    k_ln<<<M_, 256>>>(t, n1g, n1b, ln);
    gemm_mma<0, 0><<<tc_grid(2 * C_), 256, GEMM_SMEM>>>(ln, cattn_qkv_w + (size_t)C_ * C_,
                                                        nullptr, q2, nullptr, nullptr,
                                                        M_, 2 * C_, C_);
    k_fattn<1><<<fa_grid, 512, FATT_SMEM>>>(q1, C_, q2, 2 * C_, 0, C_, ob, at);
    k_headsum<<<(int)((SZ_ASUM + 255) / 256), 256>>>(at, as_);
    // sc = arf(proj(o)+b) ; s += sc
    gemm_mma<2, 1><<<tc_grid(C_), 256, GEMM_SMEM>>>(ob, cattn_proj_w, cattn_proj_b, sc,
                                                    s, s, M_, C_, C_);
    k_ln<<<M_, 256>>>(sc, n2g, n2b, ln);
    gemm_mma<1, 0><<<tc_grid(HID_), 256, GEMM_SMEM>>>(ln, fc1_w, fc1_b, hd,
                                                      nullptr, nullptr, M_, HID_, C_);
    // out_src = s + fc2(hd)+b
    gemm_mma<0, 2><<<tc_grid(C_), 256, GEMM_SMEM>>>(hd, fc2_w, fc2_b, out_src,
                                                    nullptr, s, M_, C_, HID_);

    // ---- gate + tgt out ----
    k_heat<<<(B_ * N_ + 255) / 256, 256>>>(as_, ht);
    k_tgt_out<<<EW, 256>>>(t, saw, ht, out_tgt);

    // ---- attm out ----
    k_attm<<<(int)(((size_t)B_ * 256 * 256 + 255) / 256), 256>>>(as_, out_attm);
}

// round 12
// speedup vs baseline: 1.4971x; 1.4971x over previous
#include <cuda_runtime.h>
#include <cuda_bf16.h>
#include <math.h>
#include <stdint.h>

// ---------------- problem constants ----------------
constexpr int B_  = 64;
constexpr int N_  = 257;
constexpr int C_  = 768;
constexpr int H_  = 12;
constexpr int D_  = 64;           // C_/H_
constexpr int HID_ = 3072;
constexpr int M_  = B_ * N_;      // 16448 rows
constexpr int C3_ = 3 * C_;       // 2304

constexpr size_t SZ_BNC  = (size_t)M_ * C_;
constexpr size_t SZ_QKV  = (size_t)M_ * C3_;
constexpr size_t SZ_ATT  = (size_t)B_ * H_ * N_ * N_;
constexpr size_t SZ_HID  = (size_t)M_ * HID_;
constexpr size_t SZ_ASUM = (size_t)B_ * N_ * N_;

// ---------------- device scratch (static, no allocs) ----------------
__device__ float g_s   [SZ_BNC];
__device__ float g_t   [SZ_BNC];
__device__ float g_ln  [SZ_BNC];
__device__ float g_q1  [SZ_QKV];
__device__ float g_q2  [SZ_QKV];
__device__ float g_att [SZ_ATT];
__device__ float g_o   [SZ_BNC];
__device__ float g_sc  [SZ_BNC];
__device__ float g_hid [SZ_HID];
__device__ float g_asum[SZ_ASUM];
__device__ float g_heat[(size_t)B_ * N_];

// ================= helpers =================
__device__ __forceinline__ uint32_t smem_u32(const void* p) {
    uint32_t a;
    asm("{ .reg .u64 t; cvta.to.shared.u64 t, %1; cvt.u32.u64 %0, t; }"
        : "=r"(a) : "l"(p));
    return a;
}

#define SW128(o) ((o) ^ (((o) >> 3) & 0x70))

#define LDSM_X4(r0, r1, r2, r3, addr) \
    asm volatile("ldmatrix.sync.aligned.m8n8.x4.shared.b16 {%0,%1,%2,%3}, [%4];" \
        : "=r"(r0), "=r"(r1), "=r"(r2), "=r"(r3) : "r"(addr))

#define LDSM_X2(r0, r1, addr) \
    asm volatile("ldmatrix.sync.aligned.m8n8.x2.shared.b16 {%0,%1}, [%2];" \
        : "=r"(r0), "=r"(r1) : "r"(addr))

#define MMA16816(d, a, b0, b1) \
    asm volatile("mma.sync.aligned.m16n8k16.row.col.f32.bf16.bf16.f32 " \
        "{%0,%1,%2,%3},{%4,%5,%6,%7},{%8,%9},{%0,%1,%2,%3};" \
        : "+f"((d)[0]), "+f"((d)[1]), "+f"((d)[2]), "+f"((d)[3]) \
        : "r"((a)[0]), "r"((a)[1]), "r"((a)[2]), "r"((a)[3]), "r"(b0), "r"(b1))

#define MMA_TF32(d, a, b0, b1) \
    asm volatile("mma.sync.aligned.m16n8k8.row.col.f32.tf32.tf32.f32 " \
        "{%0,%1,%2,%3},{%4,%5,%6,%7},{%8,%9},{%0,%1,%2,%3};" \
        : "+f"((d)[0]), "+f"((d)[1]), "+f"((d)[2]), "+f"((d)[3]) \
        : "r"((a)[0]), "r"((a)[1]), "r"((a)[2]), "r"((a)[3]), "r"(b0), "r"(b1))

__device__ __forceinline__ uint32_t f2tf(float f) {
    uint32_t r;
    asm("cvt.rna.tf32.f32 %0, %1;" : "=r"(r) : "f"(f));
    return r;
}

// split one fp32 x8 into hi/lo bf16x2 quads
__device__ __forceinline__ void cvt_hilo8(const float* x, uint4& hq, uint4& lq) {
    uint32_t hp[4], lp[4];
#pragma unroll
    for (int i = 0; i < 4; i++) {
        float a = x[2 * i], b = x[2 * i + 1];
        __nv_bfloat162 h2 = __float22bfloat162_rn(make_float2(a, b));
        uint32_t h = *(uint32_t*)&h2;
        hp[i] = h;
        float fa = __uint_as_float(h << 16);
        float fb = __uint_as_float(h & 0xFFFF0000u);
        __nv_bfloat162 l2 = __float22bfloat162_rn(make_float2(a - fa, b - fb));
        lp[i] = *(uint32_t*)&l2;
    }
    hq = make_uint4(hp[0], hp[1], hp[2], hp[3]);
    lq = make_uint4(lp[0], lp[1], lp[2], lp[3]);
}

__device__ __forceinline__ float arf_f(float v) {
    float ep = expf(v), en = expf(-v), en4 = expf(-v - 4.0f);
    float tmp = (ep - en) / (ep + en4);
    return tmp < 0.0f ? 0.0f : tmp;
}

// ================= split-bf16 mma.sync GEMM =================
// ACT: 0 none, 1 gelu(exact erf), 2 arf
// MODE: 0: C=v ; 1: C=v, C2=R+v ; 2: C=R+v
constexpr uint32_t T_AH = 0;
constexpr uint32_t T_AL = 8192;
constexpr uint32_t T_BH = 16384;
constexpr uint32_t T_BL = 24576;
constexpr uint32_t STAGE = 32768;
constexpr int GEMM_SMEM = 65536;

template<int ACT, int MODE>
__global__ __launch_bounds__(256, 1)
void gemm_mma(const float* __restrict__ A, const float* __restrict__ W,
              const float* __restrict__ bias, float* __restrict__ Cmat,
              float* __restrict__ C2, const float* __restrict__ R,
              int M, int Nn, int K) {
    extern __shared__ __align__(1024) char smem[];
    const uint32_t sb = smem_u32(smem);
    const int tid  = threadIdx.x;
    const int wid  = tid >> 5;
    const int lane = tid & 31;
    const int bm   = blockIdx.y * 128;
    const int bn   = blockIdx.x * 128;
    const int wm   = (wid & 3) * 32;
    const int wn   = (wid >> 2) * 64;

    const int lr = tid >> 1;
    const int lk = (tid & 1) * 16;
    const bool aOk = (bm + lr) < M;
    const float* Ap = A + (size_t)(bm + lr) * K + lk;
    const float* Wp = W + (size_t)(bn + lr) * K + lk;

    float acc[2][8][4];
#pragma unroll
    for (int i = 0; i < 2; i++)
#pragma unroll
        for (int j = 0; j < 8; j++)
#pragma unroll
            for (int r = 0; r < 4; r++) acc[i][j][r] = 0.f;

    float ra[16], rb[16];

#pragma unroll
    for (int u = 0; u < 2; ++u) {
        if (aOk) {
            float4 v0 = *(const float4*)(Ap + u * 8);
            float4 v1 = *(const float4*)(Ap + u * 8 + 4);
            ra[u*8+0]=v0.x; ra[u*8+1]=v0.y; ra[u*8+2]=v0.z; ra[u*8+3]=v0.w;
            ra[u*8+4]=v1.x; ra[u*8+5]=v1.y; ra[u*8+6]=v1.z; ra[u*8+7]=v1.w;
        } else {
#pragma unroll
            for (int q = 0; q < 8; q++) ra[u*8+q] = 0.f;
        }
        float4 w0 = *(const float4*)(Wp + u * 8);
        float4 w1 = *(const float4*)(Wp + u * 8 + 4);
        rb[u*8+0]=w0.x; rb[u*8+1]=w0.y; rb[u*8+2]=w0.z; rb[u*8+3]=w0.w;
        rb[u*8+4]=w1.x; rb[u*8+5]=w1.y; rb[u*8+6]=w1.z; rb[u*8+7]=w1.w;
    }
    {
        const uint32_t soff = lr * 64u;
#pragma unroll
        for (int u = 0; u < 2; ++u) {
            uint32_t off = soff + (uint32_t)(lk + u * 8) * 2u;
            uint32_t sw = SW128(off);
            uint4 hq, lq;
            cvt_hilo8(&ra[u * 8], hq, lq);
            *(uint4*)(smem + T_AH + sw) = hq;
            *(uint4*)(smem + T_AL + sw) = lq;
            cvt_hilo8(&rb[u * 8], hq, lq);
            *(uint4*)(smem + T_BH + sw) = hq;
            *(uint4*)(smem + T_BL + sw) = lq;
        }
    }
    __syncthreads();

    const int nit = K >> 5;
    for (int it = 0; it < nit; ++it) {
        if (it + 1 < nit) {
            const int k0 = (it + 1) << 5;
#pragma unroll
            for (int u = 0; u < 2; ++u) {
                if (aOk) {
                    float4 v0 = *(const float4*)(Ap + k0 + u * 8);
                    float4 v1 = *(const float4*)(Ap + k0 + u * 8 + 4);
                    ra[u*8+0]=v0.x; ra[u*8+1]=v0.y; ra[u*8+2]=v0.z; ra[u*8+3]=v0.w;
                    ra[u*8+4]=v1.x; ra[u*8+5]=v1.y; ra[u*8+6]=v1.z; ra[u*8+7]=v1.w;
                } else {
#pragma unroll
                    for (int q = 0; q < 8; q++) ra[u*8+q] = 0.f;
                }
                float4 w0 = *(const float4*)(Wp + k0 + u * 8);
                float4 w1 = *(const float4*)(Wp + k0 + u * 8 + 4);
                rb[u*8+0]=w0.x; rb[u*8+1]=w0.y; rb[u*8+2]=w0.z; rb[u*8+3]=w0.w;
                rb[u*8+4]=w1.x; rb[u*8+5]=w1.y; rb[u*8+6]=w1.z; rb[u*8+7]=w1.w;
            }
        }

        const uint32_t stb = sb + (uint32_t)(it & 1) * STAGE;
#pragma unroll
        for (int ks = 0; ks < 2; ++ks) {
            const int kk = ks * 16;
            uint32_t ah[2][4], al[2][4];
#pragma unroll
            for (int mt = 0; mt < 2; ++mt) {
                uint32_t off = (uint32_t)(wm + mt * 16 + (lane & 15)) * 64u
                             + (uint32_t)(kk + (lane >> 4) * 8) * 2u;
                uint32_t sw = SW128(off);
                LDSM_X4(ah[mt][0], ah[mt][1], ah[mt][2], ah[mt][3], stb + T_AH + sw);
                LDSM_X4(al[mt][0], al[mt][1], al[mt][2], al[mt][3], stb + T_AL + sw);
            }
            uint32_t bh_[8][2], bl_[8][2];
#pragma unroll
            for (int nt = 0; nt < 8; ++nt) {
                const int l8 = lane & 15;
                uint32_t boff = (uint32_t)(wn + nt * 8 + (l8 & 7)) * 64u
                              + (uint32_t)(kk + ((l8 >> 3) & 1) * 8) * 2u;
                uint32_t bsw = SW128(boff);
                LDSM_X2(bh_[nt][0], bh_[nt][1], stb + T_BH + bsw);
                LDSM_X2(bl_[nt][0], bl_[nt][1], stb + T_BL + bsw);
            }
            // term-major order: consecutive MMAs hit different accumulators
#pragma unroll
            for (int nt = 0; nt < 8; ++nt) {
                MMA16816(acc[0][nt], ah[0], bh_[nt][0], bh_[nt][1]);
                MMA16816(acc[1][nt], ah[1], bh_[nt][0], bh_[nt][1]);
            }
#pragma unroll
            for (int nt = 0; nt < 8; ++nt) {
                MMA16816(acc[0][nt], ah[0], bl_[nt][0], bl_[nt][1]);
                MMA16816(acc[1][nt], ah[1], bl_[nt][0], bl_[nt][1]);
            }
#pragma unroll
            for (int nt = 0; nt < 8; ++nt) {
                MMA16816(acc[0][nt], al[0], bh_[nt][0], bh_[nt][1]);
                MMA16816(acc[1][nt], al[1], bh_[nt][0], bh_[nt][1]);
            }
        }

        if (it + 1 < nit) {
            const uint32_t base = (uint32_t)((it + 1) & 1) * STAGE;
            const uint32_t soff = lr * 64u;
#pragma unroll
            for (int u = 0; u < 2; ++u) {
                uint32_t off = soff + (uint32_t)(lk + u * 8) * 2u;
                uint32_t sw = SW128(off);
                uint4 hq, lq;
                cvt_hilo8(&ra[u * 8], hq, lq);
                *(uint4*)(smem + base + T_AH + sw) = hq;
                *(uint4*)(smem + base + T_AL + sw) = lq;
                cvt_hilo8(&rb[u * 8], hq, lq);
                *(uint4*)(smem + base + T_BH + sw) = hq;
                *(uint4*)(smem + base + T_BL + sw) = lq;
            }
        }
        __syncthreads();
    }

#pragma unroll
    for (int mt = 0; mt < 2; ++mt) {
#pragma unroll
        for (int half = 0; half < 2; ++half) {
            const int row = bm + wm + mt * 16 + (lane >> 2) + half * 8;
            if (row < M) {
#pragma unroll
                for (int nt = 0; nt < 8; ++nt) {
                    const int col = bn + wn + nt * 8 + (lane & 3) * 2;
                    float v0 = acc[mt][nt][half * 2 + 0];
                    float v1 = acc[mt][nt][half * 2 + 1];
                    if (bias) { v0 += bias[col]; v1 += bias[col + 1]; }
                    if (ACT == 1) {
                        v0 = 0.5f * v0 * (1.0f + erff(v0 * 0.70710678118654752f));
                        v1 = 0.5f * v1 * (1.0f + erff(v1 * 0.70710678118654752f));
                    } else if (ACT == 2) {
                        v0 = arf_f(v0);
                        v1 = arf_f(v1);
                    }
                    const size_t oidx = (size_t)row * Nn + col;
                    if (MODE == 0) {
                        *(float2*)&Cmat[oidx] = make_float2(v0, v1);
                    } else if (MODE == 1) {
                        float2 r = *(const float2*)&R[oidx];
                        *(float2*)&Cmat[oidx] = make_float2(v0, v1);
                        *(float2*)&C2[oidx]   = make_float2(r.x + v0, r.y + v1);
                    } else {
                        float2 r = *(const float2*)&R[oidx];
                        *(float2*)&Cmat[oidx] = make_float2(r.x + v0, r.y + v1);
                    }
                }
            }
        }
    }
}

// ================= fused flash attention (tf32 mma, 512 thr) =================
// One CTA = one (b,h) x 64 q-rows. 16 warps: wq=wid&3 (16 q-rows each),
// wk=wid>>2 splits keys (phase1, 4 chunks) / d (phase3, 4x16).
constexpr int FA_NK  = 264;
constexpr int FA_KST = 68;    // Q/K stride  (68 % 32 == 4  -> conflict-free)
constexpr int FA_SST = 268;   // S/Vt stride (268 % 32 == 12 -> conflict-free)
constexpr int FA_OFF_Q = 0;                          // 64 x 68 (tf32 bits)
constexpr int FA_OFF_K = 64 * FA_KST;                // 264 x 68 (Vt 64 x 268 overlays)
constexpr int FA_OFF_S = FA_OFF_K + FA_NK * FA_KST;  // 64 x 268 (f32)
constexpr int FA_FLOATS = FA_OFF_S + 64 * FA_SST;
constexpr int FATT_SMEM = FA_FLOATS * 4;             // 157,824 B

template<int WRITE_P>
__global__ __launch_bounds__(512, 1)
void k_fattn(const float* __restrict__ qsrc, int qs,
             const float* __restrict__ kvsrc, int kvs, int koff, int voff,
             float* __restrict__ o, float* __restrict__ pout) {
    extern __shared__ __align__(16) float fs[];
    uint32_t* Qs = (uint32_t*)(fs + FA_OFF_Q);
    uint32_t* Ks = (uint32_t*)(fs + FA_OFF_K);
    float*    Ss = fs + FA_OFF_S;

    const int q0 = blockIdx.x * 64;
    const int bh = blockIdx.y;
    const int b = bh / H_, h = bh % H_;
    const int tid = threadIdx.x;
    const int wid = tid >> 5;
    const int lane = tid & 31;
    const int gid = lane >> 2;
    const int tig = lane & 3;
    const int wq = wid & 3;
    const int wk = wid >> 2;        // 0..3
    const int r0 = wq * 16;

    const float* Qg = qsrc + (size_t)b * N_ * qs + h * D_;
    const float* Kg = kvsrc + (size_t)b * N_ * kvs + koff + h * D_;
    const float* Vg = kvsrc + (size_t)b * N_ * kvs + voff + h * D_;

    // ---- load + convert Q (64x64) and K (264x64) to tf32 bits ----
    for (int idx = tid; idx < 64 * 64; idx += 512) {
        int r = idx >> 6, d = idx & 63;
        int q = q0 + r;
        Qs[r * FA_KST + d] = (q < N_) ? f2tf(Qg[(size_t)q * qs + d]) : 0u;
    }
    for (int idx = tid; idx < FA_NK * 64; idx += 512) {
        int r = idx >> 6, d = idx & 63;
        Ks[r * FA_KST + d] = (r < N_) ? f2tf(Kg[(size_t)r * kvs + d]) : 0u;
    }
    __syncthreads();

    // ---- phase 1: S = 0.125 * Q K^T ----
    {
        uint32_t a[8][4];
#pragma unroll
        for (int ks = 0; ks < 8; ++ks) {
            a[ks][0] = Qs[(r0 + gid)     * FA_KST + ks * 8 + tig];
            a[ks][1] = Qs[(r0 + gid + 8) * FA_KST + ks * 8 + tig];
            a[ks][2] = Qs[(r0 + gid)     * FA_KST + ks * 8 + 4 + tig];
            a[ks][3] = Qs[(r0 + gid + 8) * FA_KST + ks * 8 + 4 + tig];
        }
        const int g0 = wk * 8;
        const int g1 = (wk == 3) ? 33 : g0 + 8;
        int g = g0;
        for (; g + 4 <= g1; g += 4) {
            float c[4][4];
#pragma unroll
            for (int j = 0; j < 4; ++j)
#pragma unroll
                for (int r = 0; r < 4; ++r) c[j][r] = 0.f;
#pragma unroll
            for (int ks = 0; ks < 8; ++ks) {
#pragma unroll
                for (int j = 0; j < 4; ++j) {
                    uint32_t b0 = Ks[((g + j) * 8 + gid) * FA_KST + ks * 8 + tig];
                    uint32_t b1 = Ks[((g + j) * 8 + gid) * FA_KST + ks * 8 + 4 + tig];
                    MMA_TF32(c[j], a[ks], b0, b1);
                }
            }
#pragma unroll
            for (int j = 0; j < 4; ++j) {
                Ss[(r0 + gid)     * FA_SST + (g + j) * 8 + tig * 2]     = c[j][0] * 0.125f;
                Ss[(r0 + gid)     * FA_SST + (g + j) * 8 + tig * 2 + 1] = c[j][1] * 0.125f;
                Ss[(r0 + gid + 8) * FA_SST + (g + j) * 8 + tig * 2]     = c[j][2] * 0.125f;
                Ss[(r0 + gid + 8) * FA_SST + (g + j) * 8 + tig * 2 + 1] = c[j][3] * 0.125f;
            }
        }
        for (; g < g1; ++g) {
            float c[4] = {0.f, 0.f, 0.f, 0.f};
#pragma unroll
            for (int ks = 0; ks < 8; ++ks) {
                uint32_t b0 = Ks[(g * 8 + gid) * FA_KST + ks * 8 + tig];
                uint32_t b1 = Ks[(g * 8 + gid) * FA_KST + ks * 8 + 4 + tig];
                MMA_TF32(c, a[ks], b0, b1);
            }
            Ss[(r0 + gid)     * FA_SST + g * 8 + tig * 2]     = c[0] * 0.125f;
            Ss[(r0 + gid)     * FA_SST + g * 8 + tig * 2 + 1] = c[1] * 0.125f;
            Ss[(r0 + gid + 8) * FA_SST + g * 8 + tig * 2]     = c[2] * 0.125f;
            Ss[(r0 + gid + 8) * FA_SST + g * 8 + tig * 2 + 1] = c[3] * 0.125f;
        }
    }
    __syncthreads();

    // ---- phase 2: softmax (4 rows per warp, 16 warps) ----
#pragma unroll 1
    for (int rr = 0; rr < 4; ++rr) {
        const int row = wid * 4 + rr;
        const int q = q0 + row;
        if (q >= N_) continue;
        float* Sr = Ss + (size_t)row * FA_SST;
        float m = -1e30f;
        for (int c = lane; c < N_; c += 32) m = fmaxf(m, Sr[c]);
#pragma unroll
        for (int off = 16; off > 0; off >>= 1)
            m = fmaxf(m, __shfl_xor_sync(0xFFFFFFFF, m, off));
        float sum = 0.f;
        for (int c = lane; c < N_; c += 32) {
            float e = expf(Sr[c] - m);
            Sr[c] = e;
            sum += e;
        }
#pragma unroll
        for (int off = 16; off > 0; off >>= 1)
            sum += __shfl_xor_sync(0xFFFFFFFF, sum, off);
        const float inv = 1.0f / sum;
        for (int c = lane; c < FA_NK; c += 32) {
            float p = (c < N_) ? Sr[c] * inv : 0.f;
            Sr[c] = p;
            if (WRITE_P && c < N_)
                pout[(size_t)bh * N_ * N_ + (size_t)q * N_ + c] = p;
        }
    }
    __syncthreads();

    // ---- phase 3: Vt load (tf32), O = P V (2-term split on P) ----
    uint32_t* Vt = Ks;
    for (int idx = tid; idx < FA_NK * 64; idx += 512) {
        int key = idx >> 6, d = idx & 63;
        Vt[d * FA_SST + key] = (key < N_) ? f2tf(Vg[(size_t)key * kvs + d]) : 0u;
    }
    __syncthreads();

    float oa[2][4];
#pragma unroll
    for (int nt = 0; nt < 2; ++nt)
#pragma unroll
        for (int r = 0; r < 4; ++r) oa[nt][r] = 0.f;

#pragma unroll 1
    for (int ks = 0; ks < 33; ++ks) {
        float p0 = Ss[(r0 + gid)     * FA_SST + ks * 8 + tig];
        float p1 = Ss[(r0 + gid + 8) * FA_SST + ks * 8 + tig];
        float p2 = Ss[(r0 + gid)     * FA_SST + ks * 8 + 4 + tig];
        float p3 = Ss[(r0 + gid + 8) * FA_SST + ks * 8 + 4 + tig];
        uint32_t ah[4], al[4];
        ah[0] = f2tf(p0); al[0] = __float_as_uint(p0 - __uint_as_float(ah[0]));
        ah[1] = f2tf(p1); al[1] = __float_as_uint(p1 - __uint_as_float(ah[1]));
        ah[2] = f2tf(p2); al[2] = __float_as_uint(p2 - __uint_as_float(ah[2]));
        ah[3] = f2tf(p3); al[3] = __float_as_uint(p3 - __uint_as_float(ah[3]));
        uint32_t vb[2][2];
#pragma unroll
        for (int nt = 0; nt < 2; ++nt) {
            vb[nt][0] = Vt[(wk * 16 + nt * 8 + gid) * FA_SST + ks * 8 + tig];
            vb[nt][1] = Vt[(wk * 16 + nt * 8 + gid) * FA_SST + ks * 8 + 4 + tig];
        }
#pragma unroll
        for (int nt = 0; nt < 2; ++nt) MMA_TF32(oa[nt], ah, vb[nt][0], vb[nt][1]);
#pragma unroll
        for (int nt = 0; nt < 2; ++nt) MMA_TF32(oa[nt], al, vb[nt][0], vb[nt][1]);
    }

    // ---- write O ----
    {
        const int q_a = q0 + r0 + gid;
        const int q_b = q_a + 8;
#pragma unroll
        for (int nt = 0; nt < 2; ++nt) {
            const int col = h * D_ + wk * 16 + nt * 8 + tig * 2;
            if (q_a < N_)
                *(float2*)&o[((size_t)(b * N_ + q_a)) * C_ + col] =
                    make_float2(oa[nt][0], oa[nt][1]);
            if (q_b < N_)
                *(float2*)&o[((size_t)(b * N_ + q_b)) * C_ + col] =
                    make_float2(oa[nt][2], oa[nt][3]);
        }
    }
}

// ---------------- elementwise kernels ----------------
__global__ void k_init(const float* __restrict__ src, const float* __restrict__ tgt,
                       const float* __restrict__ pos, float* __restrict__ s,
                       float* __restrict__ t) {
    size_t i = (size_t)blockIdx.x * blockDim.x + threadIdx.x;
    if (i >= SZ_BNC) return;
    size_t nc = i % ((size_t)N_ * C_);
    s[i] = src[i] + pos[nc];
    t[i] = tgt[i];
}

// ---------------- layernorm ----------------
__global__ void k_ln(const float* __restrict__ x, const float* __restrict__ g,
                     const float* __restrict__ b, float* __restrict__ y) {
    int row = blockIdx.x;
    int tid = threadIdx.x;
    const float* xr = x + (size_t)row * C_;
    float s = 0.f, q = 0.f;
    for (int i = tid; i < C_; i += 256) { float v = xr[i]; s += v; q += v * v; }
    __shared__ float rs[256], rq[256];
    rs[tid] = s; rq[tid] = q; __syncthreads();
    for (int o = 128; o > 0; o >>= 1) {
        if (tid < o) { rs[tid] += rs[tid + o]; rq[tid] += rq[tid + o]; }
        __syncthreads();
    }
    float mean = rs[0] * (1.0f / C_);
    float var  = rq[0] * (1.0f / C_) - mean * mean;
    float inv  = rsqrtf(var + 1e-5f);
    float* yr = y + (size_t)row * C_;
    for (int i = tid; i < C_; i += 256)
        yr[i] = (xr[i] - mean) * inv * g[i] + b[i];
}

// ---------------- head sum ----------------
__global__ void k_headsum(const float* __restrict__ attn, float* __restrict__ asum) {
    size_t idx = (size_t)blockIdx.x * 256 + threadIdx.x;
    if (idx >= SZ_ASUM) return;
    size_t b = idx / ((size_t)N_ * N_);
    size_t r = idx % ((size_t)N_ * N_);
    float s = 0.f;
    for (int h = 0; h < H_; h++) s += attn[((size_t)(b * H_ + h)) * N_ * N_ + r];
    asum[idx] = s;
}

// ---------------- heat ----------------
__global__ void k_heat(const float* __restrict__ asum, float* __restrict__ heat) {
    int idx = blockIdx.x * 256 + threadIdx.x;
    if (idx >= B_ * N_) return;
    int b = idx / N_, m = idx % N_;
    const float* p = asum + (size_t)b * N_ * N_ + m;
    float s = 0.f;
    for (int n = 0; n < N_; n++) s += p[(size_t)n * N_];
    heat[idx] = s * (1.0f / N_);
}

// ---------------- tgt output ----------------
__global__ void k_tgt_out(const float* __restrict__ t, const float* __restrict__ saw,
                          const float* __restrict__ heat, float* __restrict__ out) {
    size_t i = (size_t)blockIdx.x * 256 + threadIdx.x;
    if (i >= SZ_BNC) return;
    int row = (int)(i / C_);
    int c   = (int)(i % C_);
    float gate = 1.0f / (1.0f + expf(-heat[row]));
    float tv = t[i];
    out[i] = tv + tv * saw[c] * gate;
}

// ---------------- attm copy ----------------
__global__ void k_attm(const float* __restrict__ asum, float* __restrict__ out) {
    size_t idx = (size_t)blockIdx.x * 256 + threadIdx.x;
    size_t total = (size_t)B_ * 256 * 256;
    if (idx >= total) return;
    size_t b = idx / 65536;
    size_t r = idx % 65536;
    int i = (int)(r >> 8), j = (int)(r & 255);
    out[idx] = asum[(size_t)b * N_ * N_ + (size_t)(i + 1) * N_ + (j + 1)];
}

// ---------------- host orchestration ----------------
static inline dim3 tc_grid(int Nn) { return dim3(Nn / 128, (M_ + 127) / 128); }

extern "C" void kernel_launch(void* const* d_in, const int* in_sizes, int n_in,
                              void* d_out, int out_size) {
    const float* in_src   = (const float*)d_in[0];
    const float* in_tgt   = (const float*)d_in[1];
    const float* sattn_qkv_w  = (const float*)d_in[2];
    const float* sattn_proj_w = (const float*)d_in[3];
    const float* sattn_proj_b = (const float*)d_in[4];
    const float* cattn_qkv_w  = (const float*)d_in[5];
    const float* cattn_proj_w = (const float*)d_in[6];
    const float* cattn_proj_b = (const float*)d_in[7];
    const float* n1g = (const float*)d_in[8];
    const float* n1b = (const float*)d_in[9];
    const float* n2g = (const float*)d_in[10];
    const float* n2b = (const float*)d_in[11];
    const float* fc1_w = (const float*)d_in[12];
    const float* fc1_b = (const float*)d_in[13];
    const float* fc2_w = (const float*)d_in[14];
    const float* fc2_b = (const float*)d_in[15];
    const float* saw   = (const float*)d_in[16];
    const float* pos   = (const float*)d_in[17];

    float *s, *t, *ln, *q1, *q2, *at, *ob, *sc, *hd, *as_, *ht;
    cudaGetSymbolAddress((void**)&s,   g_s);
    cudaGetSymbolAddress((void**)&t,   g_t);
    cudaGetSymbolAddress((void**)&ln,  g_ln);
    cudaGetSymbolAddress((void**)&q1,  g_q1);
    cudaGetSymbolAddress((void**)&q2,  g_q2);
    cudaGetSymbolAddress((void**)&at,  g_att);
    cudaGetSymbolAddress((void**)&ob,  g_o);
    cudaGetSymbolAddress((void**)&sc,  g_sc);
    cudaGetSymbolAddress((void**)&hd,  g_hid);
    cudaGetSymbolAddress((void**)&as_, g_asum);
    cudaGetSymbolAddress((void**)&ht,  g_heat);

    cudaFuncSetAttribute((const void*)gemm_mma<0, 0>,
                         cudaFuncAttributeMaxDynamicSharedMemorySize, GEMM_SMEM);
    cudaFuncSetAttribute((const void*)gemm_mma<0, 1>,
                         cudaFuncAttributeMaxDynamicSharedMemorySize, GEMM_SMEM);
    cudaFuncSetAttribute((const void*)gemm_mma<0, 2>,
                         cudaFuncAttributeMaxDynamicSharedMemorySize, GEMM_SMEM);
    cudaFuncSetAttribute((const void*)gemm_mma<1, 0>,
                         cudaFuncAttributeMaxDynamicSharedMemorySize, GEMM_SMEM);
    cudaFuncSetAttribute((const void*)gemm_mma<2, 1>,
                         cudaFuncAttributeMaxDynamicSharedMemorySize, GEMM_SMEM);
    cudaFuncSetAttribute((const void*)k_fattn<0>,
                         cudaFuncAttributeMaxDynamicSharedMemorySize, FATT_SMEM);
    cudaFuncSetAttribute((const void*)k_fattn<1>,
                         cudaFuncAttributeMaxDynamicSharedMemorySize, FATT_SMEM);

    float* out_src  = (float*)d_out;
    float* out_tgt  = out_src + SZ_BNC;
    float* out_attm = out_tgt + SZ_BNC;

    const int EW = (int)((SZ_BNC + 255) / 256);
    dim3 fa_grid((N_ + 63) / 64, B_ * H_);

    // ---- src = src + pos; t = tgt ----
    k_init<<<EW, 256>>>(in_src, in_tgt, pos, s, t);

    // ---- self attention on src ----
    k_ln<<<M_, 256>>>(s, n1g, n1b, ln);
    gemm_mma<0, 0><<<tc_grid(C3_), 256, GEMM_SMEM>>>(ln, sattn_qkv_w, nullptr, q1,
                                                     nullptr, nullptr, M_, C3_, C_);
    k_fattn<0><<<fa_grid, 512, FATT_SMEM>>>(q1, C3_, q1, C3_, C_, 2 * C_, ob, nullptr);
    // sc = proj(o)+b ; s += sc
    gemm_mma<0, 1><<<tc_grid(C_), 256, GEMM_SMEM>>>(ob, sattn_proj_w, sattn_proj_b, sc,
                                                    s, s, M_, C_, C_);
    k_ln<<<M_, 256>>>(sc, n2g, n2b, ln);
    gemm_mma<1, 0><<<tc_grid(HID_), 256, GEMM_SMEM>>>(ln, fc1_w, fc1_b, hd,
                                                      nullptr, nullptr, M_, HID_, C_);
    // s += fc2(hd)+b
    gemm_mma<0, 2><<<tc_grid(C_), 256, GEMM_SMEM>>>(hd, fc2_w, fc2_b, s,
                                                    nullptr, s, M_, C_, HID_);

    // ---- self attention on tgt ----
    k_ln<<<M_, 256>>>(t, n1g, n1b, ln);
    gemm_mma<0, 0><<<tc_grid(C3_), 256, GEMM_SMEM>>>(ln, sattn_qkv_w, nullptr, q1,
                                                     nullptr, nullptr, M_, C3_, C_);
    k_fattn<0><<<fa_grid, 512, FATT_SMEM>>>(q1, C3_, q1, C3_, C_, 2 * C_, ob, nullptr);
    gemm_mma<0, 1><<<tc_grid(C_), 256, GEMM_SMEM>>>(ob, sattn_proj_w, sattn_proj_b, sc,
                                                    t, t, M_, C_, C_);
    k_ln<<<M_, 256>>>(sc, n2g, n2b, ln);
    gemm_mma<1, 0><<<tc_grid(HID_), 256, GEMM_SMEM>>>(ln, fc1_w, fc1_b, hd,
                                                      nullptr, nullptr, M_, HID_, C_);
    gemm_mma<0, 2><<<tc_grid(C_), 256, GEMM_SMEM>>>(hd, fc2_w, fc2_b, t,
                                                    nullptr, t, M_, C_, HID_);

    // ---- cross attention (Q-only GEMM for src, KV-only for tgt) ----
    k_ln<<<M_, 256>>>(s, n1g, n1b, ln);
    gemm_mma<0, 0><<<tc_grid(C_), 256, GEMM_SMEM>>>(ln, cattn_qkv_w, nullptr, q1,
                                                    nullptr, nullptr, M_, C_, C_);
    k_ln<<<M_, 256>>>(t, n1g, n1b, ln);
    gemm_mma<0, 0><<<tc_grid(2 * C_), 256, GEMM_SMEM>>>(ln, cattn_qkv_w + (size_t)C_ * C_,
                                                        nullptr, q2, nullptr, nullptr,
                                                        M_, 2 * C_, C_);
    k_fattn<1><<<fa_grid, 512, FATT_SMEM>>>(q1, C_, q2, 2 * C_, 0, C_, ob, at);
    k_headsum<<<(int)((SZ_ASUM + 255) / 256), 256>>>(at, as_);
    // sc = arf(proj(o)+b) ; s += sc
    gemm_mma<2, 1><<<tc_grid(C_), 256, GEMM_SMEM>>>(ob, cattn_proj_w, cattn_proj_b, sc,
                                                    s, s, M_, C_, C_);
    k_ln<<<M_, 256>>>(sc, n2g, n2b, ln);
    gemm_mma<1, 0><<<tc_grid(HID_), 256, GEMM_SMEM>>>(ln, fc1_w, fc1_b, hd,
                                                      nullptr, nullptr, M_, HID_, C_);
    // out_src = s + fc2(hd)+b
    gemm_mma<0, 2><<<tc_grid(C_), 256, GEMM_SMEM>>>(hd, fc2_w, fc2_b, out_src,
                                                    nullptr, s, M_, C_, HID_);

    // ---- gate + tgt out ----
    k_heat<<<(B_ * N_ + 255) / 256, 256>>>(as_, ht);
    k_tgt_out<<<EW, 256>>>(t, saw, ht, out_tgt);

    // ---- attm out ----
    k_attm<<<(int)(((size_t)B_ * 256 * 256 + 255) / 256), 256>>>(as_, out_attm);
}

// round 13
// speedup vs baseline: 1.5537x; 1.0378x over previous
#include <cuda_runtime.h>
#include <cuda_bf16.h>
#include <math.h>
#include <stdint.h>

// ---------------- problem constants ----------------
constexpr int B_  = 64;
constexpr int N_  = 257;
constexpr int C_  = 768;
constexpr int H_  = 12;
constexpr int D_  = 64;           // C_/H_
constexpr int HID_ = 3072;
constexpr int M_  = B_ * N_;      // 16448 rows
constexpr int C3_ = 3 * C_;       // 2304

constexpr size_t SZ_BNC  = (size_t)M_ * C_;
constexpr size_t SZ_QKV  = (size_t)M_ * C3_;
constexpr size_t SZ_ATT  = (size_t)B_ * H_ * N_ * N_;
constexpr size_t SZ_HID  = (size_t)M_ * HID_;
constexpr size_t SZ_ASUM = (size_t)B_ * N_ * N_;

// weight scratch offsets (elements)
constexpr size_t W_SQKV  = 0;
constexpr size_t W_CQKV  = W_SQKV + (size_t)C3_ * C_;
constexpr size_t W_SPROJ = W_CQKV + (size_t)C3_ * C_;
constexpr size_t W_CPROJ = W_SPROJ + (size_t)C_ * C_;
constexpr size_t W_FC1   = W_CPROJ + (size_t)C_ * C_;
constexpr size_t W_FC2   = W_FC1 + (size_t)HID_ * C_;
constexpr size_t W_TOTAL = W_FC2 + (size_t)C_ * HID_;

// ---------------- device scratch (static, no allocs) ----------------
__device__ float g_s   [SZ_BNC];
__device__ float g_t   [SZ_BNC];
__device__ float g_q1  [SZ_QKV];
__device__ float g_q2  [SZ_QKV];
__device__ float g_att [SZ_ATT];
__device__ float g_sc  [SZ_BNC];
__device__ float g_asum[SZ_ASUM];
__device__ float g_heat[(size_t)B_ * N_];
__device__ __nv_bfloat16 g_lnh[SZ_BNC];
__device__ __nv_bfloat16 g_lnl[SZ_BNC];
__device__ __nv_bfloat16 g_obh[SZ_BNC];
__device__ __nv_bfloat16 g_obl[SZ_BNC];
__device__ __nv_bfloat16 g_hdh[SZ_HID];
__device__ __nv_bfloat16 g_hdl[SZ_HID];
__device__ __nv_bfloat16 g_wh [W_TOTAL];
__device__ __nv_bfloat16 g_wl [W_TOTAL];

// ================= helpers =================
__device__ __forceinline__ uint32_t smem_u32(const void* p) {
    uint32_t a;
    asm("{ .reg .u64 t; cvta.to.shared.u64 t, %1; cvt.u32.u64 %0, t; }"
        : "=r"(a) : "l"(p));
    return a;
}

#define SW128(o) ((o) ^ (((o) >> 3) & 0x70))

#define LDSM_X4(r0, r1, r2, r3, addr) \
    asm volatile("ldmatrix.sync.aligned.m8n8.x4.shared.b16 {%0,%1,%2,%3}, [%4];" \
        : "=r"(r0), "=r"(r1), "=r"(r2), "=r"(r3) : "r"(addr))

#define LDSM_X2(r0, r1, addr) \
    asm volatile("ldmatrix.sync.aligned.m8n8.x2.shared.b16 {%0,%1}, [%2];" \
        : "=r"(r0), "=r"(r1) : "r"(addr))

#define MMA16816(d, a, b0, b1) \
    asm volatile("mma.sync.aligned.m16n8k16.row.col.f32.bf16.bf16.f32 " \
        "{%0,%1,%2,%3},{%4,%5,%6,%7},{%8,%9},{%0,%1,%2,%3};" \
        : "+f"((d)[0]), "+f"((d)[1]), "+f"((d)[2]), "+f"((d)[3]) \
        : "r"((a)[0]), "r"((a)[1]), "r"((a)[2]), "r"((a)[3]), "r"(b0), "r"(b1))

#define MMA_TF32(d, a, b0, b1) \
    asm volatile("mma.sync.aligned.m16n8k8.row.col.f32.tf32.tf32.f32 " \
        "{%0,%1,%2,%3},{%4,%5,%6,%7},{%8,%9},{%0,%1,%2,%3};" \
        : "+f"((d)[0]), "+f"((d)[1]), "+f"((d)[2]), "+f"((d)[3]) \
        : "r"((a)[0]), "r"((a)[1]), "r"((a)[2]), "r"((a)[3]), "r"(b0), "r"(b1))

__device__ __forceinline__ uint32_t f2tf(float f) {
    uint32_t r;
    asm("cvt.rna.tf32.f32 %0, %1;" : "=r"(r) : "f"(f));
    return r;
}

// hi/lo bf16 split of a float pair (bit-identical to prior cvt_hilo8 math)
__device__ __forceinline__ void hilo2(float a, float b, uint32_t& h, uint32_t& l) {
    __nv_bfloat162 h2 = __float22bfloat162_rn(make_float2(a, b));
    h = *(uint32_t*)&h2;
    float fa = __uint_as_float(h << 16);
    float fb = __uint_as_float(h & 0xFFFF0000u);
    __nv_bfloat162 l2 = __float22bfloat162_rn(make_float2(a - fa, b - fb));
    l = *(uint32_t*)&l2;
}

__device__ __forceinline__ float arf_f(float v) {
    float ep = expf(v), en = expf(-v), en4 = expf(-v - 4.0f);
    float tmp = (ep - en) / (ep + en4);
    return tmp < 0.0f ? 0.0f : tmp;
}

// ================= weight pre-conversion =================
__global__ void k_cvtw(const float* __restrict__ w, __nv_bfloat16* __restrict__ wh,
                       __nv_bfloat16* __restrict__ wl, size_t n) {
    size_t i0 = ((size_t)blockIdx.x * 256 + threadIdx.x) * 2;
    if (i0 >= n) return;
    uint32_t h, l;
    hilo2(w[i0], w[i0 + 1], h, l);
    *(uint32_t*)(wh + i0) = h;
    *(uint32_t*)(wl + i0) = l;
}

// ================= split-bf16 mma.sync GEMM (bf16-pair inputs) =================
// ACT: 0 none, 1 gelu(exact erf), 2 arf
// MODE: 0: C=v ; 1: C=v, C2=R+v ; 2: C=R+v      (used when OUTBF==0)
// OUTBF: 1 -> write hi/lo bf16 pair to Oh/Ol instead
constexpr uint32_t T_AH = 0;
constexpr uint32_t T_AL = 8192;
constexpr uint32_t T_BH = 16384;
constexpr uint32_t T_BL = 24576;
constexpr uint32_t STAGE = 32768;
constexpr int GEMM_SMEM = 65536;

template<int ACT, int MODE, int OUTBF>
__global__ __launch_bounds__(256, 1)
void gemm_mma(const __nv_bfloat16* __restrict__ Ah, const __nv_bfloat16* __restrict__ Al,
              const __nv_bfloat16* __restrict__ Wh, const __nv_bfloat16* __restrict__ Wl,
              const float* __restrict__ bias, float* __restrict__ Cmat,
              float* __restrict__ C2, const float* __restrict__ R,
              __nv_bfloat16* __restrict__ Oh, __nv_bfloat16* __restrict__ Ol,
              int M, int Nn, int K) {
    extern __shared__ __align__(1024) char smem[];
    const uint32_t sb = smem_u32(smem);
    const int tid  = threadIdx.x;
    const int wid  = tid >> 5;
    const int lane = tid & 31;
    const int bm   = blockIdx.y * 128;
    const int bn   = blockIdx.x * 128;
    const int wm   = (wid & 3) * 32;
    const int wn   = (wid >> 2) * 64;

    const int lr = tid >> 1;
    const int lk = (tid & 1) * 16;
    const bool aOk = (bm + lr) < M;
    const __nv_bfloat16* Aph = Ah + (size_t)(bm + lr) * K + lk;
    const __nv_bfloat16* Apl = Al + (size_t)(bm + lr) * K + lk;
    const __nv_bfloat16* Wph = Wh + (size_t)(bn + lr) * K + lk;
    const __nv_bfloat16* Wpl = Wl + (size_t)(bn + lr) * K + lk;

    float acc[2][8][4];
#pragma unroll
    for (int i = 0; i < 2; i++)
#pragma unroll
        for (int j = 0; j < 8; j++)
#pragma unroll
            for (int r = 0; r < 4; r++) acc[i][j][r] = 0.f;

    uint4 sa_h[2], sa_l[2], sw_h[2], sw_l[2];
    const uint4 z4 = make_uint4(0, 0, 0, 0);

    // ---- prologue load (k0 = 0) ----
#pragma unroll
    for (int u = 0; u < 2; ++u) {
        sa_h[u] = aOk ? *(const uint4*)(Aph + u * 8) : z4;
        sa_l[u] = aOk ? *(const uint4*)(Apl + u * 8) : z4;
        sw_h[u] = *(const uint4*)(Wph + u * 8);
        sw_l[u] = *(const uint4*)(Wpl + u * 8);
    }
    {
        const uint32_t soff = lr * 64u;
#pragma unroll
        for (int u = 0; u < 2; ++u) {
            uint32_t off = soff + (uint32_t)(lk + u * 8) * 2u;
            uint32_t sw = SW128(off);
            *(uint4*)(smem + T_AH + sw) = sa_h[u];
            *(uint4*)(smem + T_AL + sw) = sa_l[u];
            *(uint4*)(smem + T_BH + sw) = sw_h[u];
            *(uint4*)(smem + T_BL + sw) = sw_l[u];
        }
    }
    __syncthreads();

    const int nit = K >> 5;
    for (int it = 0; it < nit; ++it) {
        if (it + 1 < nit) {
            const int k0 = (it + 1) << 5;
#pragma unroll
            for (int u = 0; u < 2; ++u) {
                sa_h[u] = aOk ? *(const uint4*)(Aph + k0 + u * 8) : z4;
                sa_l[u] = aOk ? *(const uint4*)(Apl + k0 + u * 8) : z4;
                sw_h[u] = *(const uint4*)(Wph + k0 + u * 8);
                sw_l[u] = *(const uint4*)(Wpl + k0 + u * 8);
            }
        }

        const uint32_t stb = sb + (uint32_t)(it & 1) * STAGE;
#pragma unroll
        for (int ks = 0; ks < 2; ++ks) {
            const int kk = ks * 16;
            uint32_t ah[2][4], al[2][4];
#pragma unroll
            for (int mt = 0; mt < 2; ++mt) {
                uint32_t off = (uint32_t)(wm + mt * 16 + (lane & 15)) * 64u
                             + (uint32_t)(kk + (lane >> 4) * 8) * 2u;
                uint32_t sw = SW128(off);
                LDSM_X4(ah[mt][0], ah[mt][1], ah[mt][2], ah[mt][3], stb + T_AH + sw);
                LDSM_X4(al[mt][0], al[mt][1], al[mt][2], al[mt][3], stb + T_AL + sw);
            }
            uint32_t bh_[8][2], bl_[8][2];
#pragma unroll
            for (int nt = 0; nt < 8; ++nt) {
                const int l8 = lane & 15;
                uint32_t boff = (uint32_t)(wn + nt * 8 + (l8 & 7)) * 64u
                              + (uint32_t)(kk + ((l8 >> 3) & 1) * 8) * 2u;
                uint32_t bsw = SW128(boff);
                LDSM_X2(bh_[nt][0], bh_[nt][1], stb + T_BH + bsw);
                LDSM_X2(bl_[nt][0], bl_[nt][1], stb + T_BL + bsw);
            }
            // term-major order: consecutive MMAs hit different accumulators
#pragma unroll
            for (int nt = 0; nt < 8; ++nt) {
                MMA16816(acc[0][nt], ah[0], bh_[nt][0], bh_[nt][1]);
                MMA16816(acc[1][nt], ah[1], bh_[nt][0], bh_[nt][1]);
            }
#pragma unroll
            for (int nt = 0; nt < 8; ++nt) {
                MMA16816(acc[0][nt], ah[0], bl_[nt][0], bl_[nt][1]);
                MMA16816(acc[1][nt], ah[1], bl_[nt][0], bl_[nt][1]);
            }
#pragma unroll
            for (int nt = 0; nt < 8; ++nt) {
                MMA16816(acc[0][nt], al[0], bh_[nt][0], bh_[nt][1]);
                MMA16816(acc[1][nt], al[1], bh_[nt][0], bh_[nt][1]);
            }
        }

        if (it + 1 < nit) {
            const uint32_t base = (uint32_t)((it + 1) & 1) * STAGE;
            const uint32_t soff = lr * 64u;
#pragma unroll
            for (int u = 0; u < 2; ++u) {
                uint32_t off = soff + (uint32_t)(lk + u * 8) * 2u;
                uint32_t sw = SW128(off);
                *(uint4*)(smem + base + T_AH + sw) = sa_h[u];
                *(uint4*)(smem + base + T_AL + sw) = sa_l[u];
                *(uint4*)(smem + base + T_BH + sw) = sw_h[u];
                *(uint4*)(smem + base + T_BL + sw) = sw_l[u];
            }
        }
        __syncthreads();
    }

#pragma unroll
    for (int mt = 0; mt < 2; ++mt) {
#pragma unroll
        for (int half = 0; half < 2; ++half) {
            const int row = bm + wm + mt * 16 + (lane >> 2) + half * 8;
            if (row < M) {
#pragma unroll
                for (int nt = 0; nt < 8; ++nt) {
                    const int col = bn + wn + nt * 8 + (lane & 3) * 2;
                    float v0 = acc[mt][nt][half * 2 + 0];
                    float v1 = acc[mt][nt][half * 2 + 1];
                    if (bias) { v0 += bias[col]; v1 += bias[col + 1]; }
                    if (ACT == 1) {
                        v0 = 0.5f * v0 * (1.0f + erff(v0 * 0.70710678118654752f));
                        v1 = 0.5f * v1 * (1.0f + erff(v1 * 0.70710678118654752f));
                    } else if (ACT == 2) {
                        v0 = arf_f(v0);
                        v1 = arf_f(v1);
                    }
                    const size_t oidx = (size_t)row * Nn + col;
                    if (OUTBF) {
                        uint32_t h, l;
                        hilo2(v0, v1, h, l);
                        *(uint32_t*)(Oh + oidx) = h;
                        *(uint32_t*)(Ol + oidx) = l;
                    } else if (MODE == 0) {
                        *(float2*)&Cmat[oidx] = make_float2(v0, v1);
                    } else if (MODE == 1) {
                        float2 r = *(const float2*)&R[oidx];
                        *(float2*)&Cmat[oidx] = make_float2(v0, v1);
                        *(float2*)&C2[oidx]   = make_float2(r.x + v0, r.y + v1);
                    } else {
                        float2 r = *(const float2*)&R[oidx];
                        *(float2*)&Cmat[oidx] = make_float2(r.x + v0, r.y + v1);
                    }
                }
            }
        }
    }
}

// ================= fused flash attention (tf32 mma, 512 thr) =================
constexpr int FA_NK  = 264;
constexpr int FA_KST = 68;
constexpr int FA_SST = 268;
constexpr int FA_OFF_Q = 0;
constexpr int FA_OFF_K = 64 * FA_KST;
constexpr int FA_OFF_S = FA_OFF_K + FA_NK * FA_KST;
constexpr int FA_FLOATS = FA_OFF_S + 64 * FA_SST;
constexpr int FATT_SMEM = FA_FLOATS * 4;             // 157,824 B

template<int WRITE_P>
__global__ __launch_bounds__(512, 1)
void k_fattn(const float* __restrict__ qsrc, int qs,
             const float* __restrict__ kvsrc, int kvs, int koff, int voff,
             __nv_bfloat16* __restrict__ oh, __nv_bfloat16* __restrict__ ol,
             float* __restrict__ pout) {
    extern __shared__ __align__(16) float fs[];
    uint32_t* Qs = (uint32_t*)(fs + FA_OFF_Q);
    uint32_t* Ks = (uint32_t*)(fs + FA_OFF_K);
    float*    Ss = fs + FA_OFF_S;

    const int q0 = blockIdx.x * 64;
    const int bh = blockIdx.y;
    const int b = bh / H_, h = bh % H_;
    const int tid = threadIdx.x;
    const int wid = tid >> 5;
    const int lane = tid & 31;
    const int gid = lane >> 2;
    const int tig = lane & 3;
    const int wq = wid & 3;
    const int wk = wid >> 2;
    const int r0 = wq * 16;

    const float* Qg = qsrc + (size_t)b * N_ * qs + h * D_;
    const float* Kg = kvsrc + (size_t)b * N_ * kvs + koff + h * D_;
    const float* Vg = kvsrc + (size_t)b * N_ * kvs + voff + h * D_;

    for (int idx = tid; idx < 64 * 64; idx += 512) {
        int r = idx >> 6, d = idx & 63;
        int q = q0 + r;
        Qs[r * FA_KST + d] = (q < N_) ? f2tf(Qg[(size_t)q * qs + d]) : 0u;
    }
    for (int idx = tid; idx < FA_NK * 64; idx += 512) {
        int r = idx >> 6, d = idx & 63;
        Ks[r * FA_KST + d] = (r < N_) ? f2tf(Kg[(size_t)r * kvs + d]) : 0u;
    }
    __syncthreads();

    // ---- phase 1: S = 0.125 * Q K^T ----
    {
        uint32_t a[8][4];
#pragma unroll
        for (int ks = 0; ks < 8; ++ks) {
            a[ks][0] = Qs[(r0 + gid)     * FA_KST + ks * 8 + tig];
            a[ks][1] = Qs[(r0 + gid + 8) * FA_KST + ks * 8 + tig];
            a[ks][2] = Qs[(r0 + gid)     * FA_KST + ks * 8 + 4 + tig];
            a[ks][3] = Qs[(r0 + gid + 8) * FA_KST + ks * 8 + 4 + tig];
        }
        const int g0 = wk * 8;
        const int g1 = (wk == 3) ? 33 : g0 + 8;
        int g = g0;
        for (; g + 4 <= g1; g += 4) {
            float c[4][4];
#pragma unroll
            for (int j = 0; j < 4; ++j)
#pragma unroll
                for (int r = 0; r < 4; ++r) c[j][r] = 0.f;
#pragma unroll
            for (int ks = 0; ks < 8; ++ks) {
#pragma unroll
                for (int j = 0; j < 4; ++j) {
                    uint32_t b0 = Ks[((g + j) * 8 + gid) * FA_KST + ks * 8 + tig];
                    uint32_t b1 = Ks[((g + j) * 8 + gid) * FA_KST + ks * 8 + 4 + tig];
                    MMA_TF32(c[j], a[ks], b0, b1);
                }
            }
#pragma unroll
            for (int j = 0; j < 4; ++j) {
                Ss[(r0 + gid)     * FA_SST + (g + j) * 8 + tig * 2]     = c[j][0] * 0.125f;
                Ss[(r0 + gid)     * FA_SST + (g + j) * 8 + tig * 2 + 1] = c[j][1] * 0.125f;
                Ss[(r0 + gid + 8) * FA_SST + (g + j) * 8 + tig * 2]     = c[j][2] * 0.125f;
                Ss[(r0 + gid + 8) * FA_SST + (g + j) * 8 + tig * 2 + 1] = c[j][3] * 0.125f;
            }
        }
        for (; g < g1; ++g) {
            float c[4] = {0.f, 0.f, 0.f, 0.f};
#pragma unroll
            for (int ks = 0; ks < 8; ++ks) {
                uint32_t b0 = Ks[(g * 8 + gid) * FA_KST + ks * 8 + tig];
                uint32_t b1 = Ks[(g * 8 + gid) * FA_KST + ks * 8 + 4 + tig];
                MMA_TF32(c, a[ks], b0, b1);
            }
            Ss[(r0 + gid)     * FA_SST + g * 8 + tig * 2]     = c[0] * 0.125f;
            Ss[(r0 + gid)     * FA_SST + g * 8 + tig * 2 + 1] = c[1] * 0.125f;
            Ss[(r0 + gid + 8) * FA_SST + g * 8 + tig * 2]     = c[2] * 0.125f;
            Ss[(r0 + gid + 8) * FA_SST + g * 8 + tig * 2 + 1] = c[3] * 0.125f;
        }
    }
    __syncthreads();

    // ---- phase 2: softmax (4 rows per warp, 16 warps) ----
#pragma unroll 1
    for (int rr = 0; rr < 4; ++rr) {
        const int row = wid * 4 + rr;
        const int q = q0 + row;
        if (q >= N_) continue;
        float* Sr = Ss + (size_t)row * FA_SST;
        float m = -1e30f;
        for (int c = lane; c < N_; c += 32) m = fmaxf(m, Sr[c]);
#pragma unroll
        for (int off = 16; off > 0; off >>= 1)
            m = fmaxf(m, __shfl_xor_sync(0xFFFFFFFF, m, off));
        float sum = 0.f;
        for (int c = lane; c < N_; c += 32) {
            float e = expf(Sr[c] - m);
            Sr[c] = e;
            sum += e;
        }
#pragma unroll
        for (int off = 16; off > 0; off >>= 1)
            sum += __shfl_xor_sync(0xFFFFFFFF, sum, off);
        const float inv = 1.0f / sum;
        for (int c = lane; c < FA_NK; c += 32) {
            float p = (c < N_) ? Sr[c] * inv : 0.f;
            Sr[c] = p;
            if (WRITE_P && c < N_)
                pout[(size_t)bh * N_ * N_ + (size_t)q * N_ + c] = p;
        }
    }
    __syncthreads();

    // ---- phase 3: Vt load (tf32), O = P V (2-term split on P) ----
    uint32_t* Vt = Ks;
    for (int idx = tid; idx < FA_NK * 64; idx += 512) {
        int key = idx >> 6, d = idx & 63;
        Vt[d * FA_SST + key] = (key < N_) ? f2tf(Vg[(size_t)key * kvs + d]) : 0u;
    }
    __syncthreads();

    float oa[2][4];
#pragma unroll
    for (int nt = 0; nt < 2; ++nt)
#pragma unroll
        for (int r = 0; r < 4; ++r) oa[nt][r] = 0.f;

#pragma unroll 1
    for (int ks = 0; ks < 33; ++ks) {
        float p0 = Ss[(r0 + gid)     * FA_SST + ks * 8 + tig];
        float p1 = Ss[(r0 + gid + 8) * FA_SST + ks * 8 + tig];
        float p2 = Ss[(r0 + gid)     * FA_SST + ks * 8 + 4 + tig];
        float p3 = Ss[(r0 + gid + 8) * FA_SST + ks * 8 + 4 + tig];
        uint32_t ah[4], al[4];
        ah[0] = f2tf(p0); al[0] = __float_as_uint(p0 - __uint_as_float(ah[0]));
        ah[1] = f2tf(p1); al[1] = __float_as_uint(p1 - __uint_as_float(ah[1]));
        ah[2] = f2tf(p2); al[2] = __float_as_uint(p2 - __uint_as_float(ah[2]));
        ah[3] = f2tf(p3); al[3] = __float_as_uint(p3 - __uint_as_float(ah[3]));
        uint32_t vb[2][2];
#pragma unroll
        for (int nt = 0; nt < 2; ++nt) {
            vb[nt][0] = Vt[(wk * 16 + nt * 8 + gid) * FA_SST + ks * 8 + tig];
            vb[nt][1] = Vt[(wk * 16 + nt * 8 + gid) * FA_SST + ks * 8 + 4 + tig];
        }
#pragma unroll
        for (int nt = 0; nt < 2; ++nt) MMA_TF32(oa[nt], ah, vb[nt][0], vb[nt][1]);
#pragma unroll
        for (int nt = 0; nt < 2; ++nt) MMA_TF32(oa[nt], al, vb[nt][0], vb[nt][1]);
    }

    // ---- write O as bf16 hi/lo pairs ----
    {
        const int q_a = q0 + r0 + gid;
        const int q_b = q_a + 8;
#pragma unroll
        for (int nt = 0; nt < 2; ++nt) {
            const int col = h * D_ + wk * 16 + nt * 8 + tig * 2;
            if (q_a < N_) {
                uint32_t hh, ll;
                hilo2(oa[nt][0], oa[nt][1], hh, ll);
                const size_t oidx = ((size_t)(b * N_ + q_a)) * C_ + col;
                *(uint32_t*)(oh + oidx) = hh;
                *(uint32_t*)(ol + oidx) = ll;
            }
            if (q_b < N_) {
                uint32_t hh, ll;
                hilo2(oa[nt][2], oa[nt][3], hh, ll);
                const size_t oidx = ((size_t)(b * N_ + q_b)) * C_ + col;
                *(uint32_t*)(oh + oidx) = hh;
                *(uint32_t*)(ol + oidx) = ll;
            }
        }
    }
}

// ---------------- elementwise kernels ----------------
__global__ void k_init(const float* __restrict__ src, const float* __restrict__ tgt,
                       const float* __restrict__ pos, float* __restrict__ s,
                       float* __restrict__ t) {
    size_t i = (size_t)blockIdx.x * blockDim.x + threadIdx.x;
    if (i >= SZ_BNC) return;
    size_t nc = i % ((size_t)N_ * C_);
    s[i] = src[i] + pos[nc];
    t[i] = tgt[i];
}

// ---------------- layernorm -> bf16 hi/lo ----------------
__global__ void k_ln(const float* __restrict__ x, const float* __restrict__ g,
                     const float* __restrict__ b, __nv_bfloat16* __restrict__ yh,
                     __nv_bfloat16* __restrict__ yl) {
    int row = blockIdx.x;
    int tid = threadIdx.x;
    const float* xr = x + (size_t)row * C_;
    float s = 0.f, q = 0.f;
    for (int i = tid; i < C_; i += 256) { float v = xr[i]; s += v; q += v * v; }
    __shared__ float rs[256], rq[256];
    rs[tid] = s; rq[tid] = q; __syncthreads();
    for (int o = 128; o > 0; o >>= 1) {
        if (tid < o) { rs[tid] += rs[tid + o]; rq[tid] += rq[tid + o]; }
        __syncthreads();
    }
    float mean = rs[0] * (1.0f / C_);
    float var  = rq[0] * (1.0f / C_) - mean * mean;
    float inv  = rsqrtf(var + 1e-5f);
    __nv_bfloat16* yhr = yh + (size_t)row * C_;
    __nv_bfloat16* ylr = yl + (size_t)row * C_;
    for (int i0 = tid * 2; i0 < C_; i0 += 512) {
        float v0 = (xr[i0]     - mean) * inv * g[i0]     + b[i0];
        float v1 = (xr[i0 + 1] - mean) * inv * g[i0 + 1] + b[i0 + 1];
        uint32_t h, l;
        hilo2(v0, v1, h, l);
        *(uint32_t*)(yhr + i0) = h;
        *(uint32_t*)(ylr + i0) = l;
    }
}

// ---------------- head sum ----------------
__global__ void k_headsum(const float* __restrict__ attn, float* __restrict__ asum) {
    size_t idx = (size_t)blockIdx.x * 256 + threadIdx.x;
    if (idx >= SZ_ASUM) return;
    size_t b = idx / ((size_t)N_ * N_);
    size_t r = idx % ((size_t)N_ * N_);
    float s = 0.f;
    for (int h = 0; h < H_; h++) s += attn[((size_t)(b * H_ + h)) * N_ * N_ + r];
    asum[idx] = s;
}

// ---------------- heat ----------------
__global__ void k_heat(const float* __restrict__ asum, float* __restrict__ heat) {
    int idx = blockIdx.x * 256 + threadIdx.x;
    if (idx >= B_ * N_) return;
    int b = idx / N_, m = idx % N_;
    const float* p = asum + (size_t)b * N_ * N_ + m;
    float s = 0.f;
    for (int n = 0; n < N_; n++) s += p[(size_t)n * N_];
    heat[idx] = s * (1.0f / N_);
}

// ---------------- tgt output ----------------
__global__ void k_tgt_out(const float* __restrict__ t, const float* __restrict__ saw,
                          const float* __restrict__ heat, float* __restrict__ out) {
    size_t i = (size_t)blockIdx.x * 256 + threadIdx.x;
    if (i >= SZ_BNC) return;
    int row = (int)(i / C_);
    int c   = (int)(i % C_);
    float gate = 1.0f / (1.0f + expf(-heat[row]));
    float tv = t[i];
    out[i] = tv + tv * saw[c] * gate;
}

// ---------------- attm copy ----------------
__global__ void k_attm(const float* __restrict__ asum, float* __restrict__ out) {
    size_t idx = (size_t)blockIdx.x * 256 + threadIdx.x;
    size_t total = (size_t)B_ * 256 * 256;
    if (idx >= total) return;
    size_t b = idx / 65536;
    size_t r = idx % 65536;
    int i = (int)(r >> 8), j = (int)(r & 255);
    out[idx] = asum[(size_t)b * N_ * N_ + (size_t)(i + 1) * N_ + (j + 1)];
}

// ---------------- host orchestration ----------------
static inline dim3 tc_grid(int Nn) { return dim3(Nn / 128, (M_ + 127) / 128); }
static inline int cvtw_grid(size_t n) { return (int)((n / 2 + 255) / 256); }

extern "C" void kernel_launch(void* const* d_in, const int* in_sizes, int n_in,
                              void* d_out, int out_size) {
    const float* in_src   = (const float*)d_in[0];
    const float* in_tgt   = (const float*)d_in[1];
    const float* sattn_qkv_w  = (const float*)d_in[2];
    const float* sattn_proj_w = (const float*)d_in[3];
    const float* sattn_proj_b = (const float*)d_in[4];
    const float* cattn_qkv_w  = (const float*)d_in[5];
    const float* cattn_proj_w = (const float*)d_in[6];
    const float* cattn_proj_b = (const float*)d_in[7];
    const float* n1g = (const float*)d_in[8];
    const float* n1b = (const float*)d_in[9];
    const float* n2g = (const float*)d_in[10];
    const float* n2b = (const float*)d_in[11];
    const float* fc1_w = (const float*)d_in[12];
    const float* fc1_b = (const float*)d_in[13];
    const float* fc2_w = (const float*)d_in[14];
    const float* fc2_b = (const float*)d_in[15];
    const float* saw   = (const float*)d_in[16];
    const float* pos   = (const float*)d_in[17];

    float *s, *t, *q1, *q2, *at, *sc, *as_, *ht;
    __nv_bfloat16 *lnh, *lnl, *obh, *obl, *hdh, *hdl, *wh, *wl;
    cudaGetSymbolAddress((void**)&s,   g_s);
    cudaGetSymbolAddress((void**)&t,   g_t);
    cudaGetSymbolAddress((void**)&q1,  g_q1);
    cudaGetSymbolAddress((void**)&q2,  g_q2);
    cudaGetSymbolAddress((void**)&at,  g_att);
    cudaGetSymbolAddress((void**)&sc,  g_sc);
    cudaGetSymbolAddress((void**)&as_, g_asum);
    cudaGetSymbolAddress((void**)&ht,  g_heat);
    cudaGetSymbolAddress((void**)&lnh, g_lnh);
    cudaGetSymbolAddress((void**)&lnl, g_lnl);
    cudaGetSymbolAddress((void**)&obh, g_obh);
    cudaGetSymbolAddress((void**)&obl, g_obl);
    cudaGetSymbolAddress((void**)&hdh, g_hdh);
    cudaGetSymbolAddress((void**)&hdl, g_hdl);
    cudaGetSymbolAddress((void**)&wh,  g_wh);
    cudaGetSymbolAddress((void**)&wl,  g_wl);

    cudaFuncSetAttribute((const void*)gemm_mma<0, 0, 0>,
                         cudaFuncAttributeMaxDynamicSharedMemorySize, GEMM_SMEM);
    cudaFuncSetAttribute((const void*)gemm_mma<0, 1, 0>,
                         cudaFuncAttributeMaxDynamicSharedMemorySize, GEMM_SMEM);
    cudaFuncSetAttribute((const void*)gemm_mma<0, 2, 0>,
                         cudaFuncAttributeMaxDynamicSharedMemorySize, GEMM_SMEM);
    cudaFuncSetAttribute((const void*)gemm_mma<1, 0, 1>,
                         cudaFuncAttributeMaxDynamicSharedMemorySize, GEMM_SMEM);
    cudaFuncSetAttribute((const void*)gemm_mma<2, 1, 0>,
                         cudaFuncAttributeMaxDynamicSharedMemorySize, GEMM_SMEM);
    cudaFuncSetAttribute((const void*)k_fattn<0>,
                         cudaFuncAttributeMaxDynamicSharedMemorySize, FATT_SMEM);
    cudaFuncSetAttribute((const void*)k_fattn<1>,
                         cudaFuncAttributeMaxDynamicSharedMemorySize, FATT_SMEM);

    float* out_src  = (float*)d_out;
    float* out_tgt  = out_src + SZ_BNC;
    float* out_attm = out_tgt + SZ_BNC;

    const int EW = (int)((SZ_BNC + 255) / 256);
    dim3 fa_grid((N_ + 63) / 64, B_ * H_);

    // ---- weight pre-conversion ----
    k_cvtw<<<cvtw_grid((size_t)C3_ * C_), 256>>>(sattn_qkv_w, wh + W_SQKV, wl + W_SQKV,
                                                 (size_t)C3_ * C_);
    k_cvtw<<<cvtw_grid((size_t)C3_ * C_), 256>>>(cattn_qkv_w, wh + W_CQKV, wl + W_CQKV,
                                                 (size_t)C3_ * C_);
    k_cvtw<<<cvtw_grid((size_t)C_ * C_), 256>>>(sattn_proj_w, wh + W_SPROJ, wl + W_SPROJ,
                                                (size_t)C_ * C_);
    k_cvtw<<<cvtw_grid((size_t)C_ * C_), 256>>>(cattn_proj_w, wh + W_CPROJ, wl + W_CPROJ,
                                                (size_t)C_ * C_);
    k_cvtw<<<cvtw_grid((size_t)HID_ * C_), 256>>>(fc1_w, wh + W_FC1, wl + W_FC1,
                                                  (size_t)HID_ * C_);
    k_cvtw<<<cvtw_grid((size_t)C_ * HID_), 256>>>(fc2_w, wh + W_FC2, wl + W_FC2,
                                                  (size_t)C_ * HID_);

    // ---- src = src + pos; t = tgt ----
    k_init<<<EW, 256>>>(in_src, in_tgt, pos, s, t);

    // ---- self attention on src ----
    k_ln<<<M_, 256>>>(s, n1g, n1b, lnh, lnl);
    gemm_mma<0, 0, 0><<<tc_grid(C3_), 256, GEMM_SMEM>>>(lnh, lnl, wh + W_SQKV, wl + W_SQKV,
        nullptr, q1, nullptr, nullptr, nullptr, nullptr, M_, C3_, C_);
    k_fattn<0><<<fa_grid, 512, FATT_SMEM>>>(q1, C3_, q1, C3_, C_, 2 * C_, obh, obl, nullptr);
    gemm_mma<0, 1, 0><<<tc_grid(C_), 256, GEMM_SMEM>>>(obh, obl, wh + W_SPROJ, wl + W_SPROJ,
        sattn_proj_b, sc, s, s, nullptr, nullptr, M_, C_, C_);
    k_ln<<<M_, 256>>>(sc, n2g, n2b, lnh, lnl);
    gemm_mma<1, 0, 1><<<tc_grid(HID_), 256, GEMM_SMEM>>>(lnh, lnl, wh + W_FC1, wl + W_FC1,
        fc1_b, nullptr, nullptr, nullptr, hdh, hdl, M_, HID_, C_);
    gemm_mma<0, 2, 0><<<tc_grid(C_), 256, GEMM_SMEM>>>(hdh, hdl, wh + W_FC2, wl + W_FC2,
        fc2_b, s, nullptr, s, nullptr, nullptr, M_, C_, HID_);

    // ---- self attention on tgt ----
    k_ln<<<M_, 256>>>(t, n1g, n1b, lnh, lnl);
    gemm_mma<0, 0, 0><<<tc_grid(C3_), 256, GEMM_SMEM>>>(lnh, lnl, wh + W_SQKV, wl + W_SQKV,
        nullptr, q1, nullptr, nullptr, nullptr, nullptr, M_, C3_, C_);
    k_fattn<0><<<fa_grid, 512, FATT_SMEM>>>(q1, C3_, q1, C3_, C_, 2 * C_, obh, obl, nullptr);
    gemm_mma<0, 1, 0><<<tc_grid(C_), 256, GEMM_SMEM>>>(obh, obl, wh + W_SPROJ, wl + W_SPROJ,
        sattn_proj_b, sc, t, t, nullptr, nullptr, M_, C_, C_);
    k_ln<<<M_, 256>>>(sc, n2g, n2b, lnh, lnl);
    gemm_mma<1, 0, 1><<<tc_grid(HID_), 256, GEMM_SMEM>>>(lnh, lnl, wh + W_FC1, wl + W_FC1,
        fc1_b, nullptr, nullptr, nullptr, hdh, hdl, M_, HID_, C_);
    gemm_mma<0, 2, 0><<<tc_grid(C_), 256, GEMM_SMEM>>>(hdh, hdl, wh + W_FC2, wl + W_FC2,
        fc2_b, t, nullptr, t, nullptr, nullptr, M_, C_, HID_);

    // ---- cross attention (Q-only GEMM for src, KV-only for tgt) ----
    k_ln<<<M_, 256>>>(s, n1g, n1b, lnh, lnl);
    gemm_mma<0, 0, 0><<<tc_grid(C_), 256, GEMM_SMEM>>>(lnh, lnl, wh + W_CQKV, wl + W_CQKV,
        nullptr, q1, nullptr, nullptr, nullptr, nullptr, M_, C_, C_);
    k_ln<<<M_, 256>>>(t, n1g, n1b, lnh, lnl);
    gemm_mma<0, 0, 0><<<tc_grid(2 * C_), 256, GEMM_SMEM>>>(lnh, lnl,
        wh + W_CQKV + (size_t)C_ * C_, wl + W_CQKV + (size_t)C_ * C_,
        nullptr, q2, nullptr, nullptr, nullptr, nullptr, M_, 2 * C_, C_);
    k_fattn<1><<<fa_grid, 512, FATT_SMEM>>>(q1, C_, q2, 2 * C_, 0, C_, obh, obl, at);
    k_headsum<<<(int)((SZ_ASUM + 255) / 256), 256>>>(at, as_);
    gemm_mma<2, 1, 0><<<tc_grid(C_), 256, GEMM_SMEM>>>(obh, obl, wh + W_CPROJ, wl + W_CPROJ,
        cattn_proj_b, sc, s, s, nullptr, nullptr, M_, C_, C_);
    k_ln<<<M_, 256>>>(sc, n2g, n2b, lnh, lnl);
    gemm_mma<1, 0, 1><<<tc_grid(HID_), 256, GEMM_SMEM>>>(lnh, lnl, wh + W_FC1, wl + W_FC1,
        fc1_b, nullptr, nullptr, nullptr, hdh, hdl, M_, HID_, C_);
    gemm_mma<0, 2, 0><<<tc_grid(C_), 256, GEMM_SMEM>>>(hdh, hdl, wh + W_FC2, wl + W_FC2,
        fc2_b, out_src, nullptr, s, nullptr, nullptr, M_, C_, HID_);

    // ---- gate + tgt out ----
    k_heat<<<(B_ * N_ + 255) / 256, 256>>>(as_, ht);
    k_tgt_out<<<EW, 256>>>(t, saw, ht, out_tgt);

    // ---- attm out ----
    k_attm<<<(int)(((size_t)B_ * 256 * 256 + 255) / 256), 256>>>(as_, out_attm);
}

// round 14
// speedup vs baseline: 1.6789x; 1.0806x over previous
#include <cuda_runtime.h>
#include <cuda_bf16.h>
#include <math.h>
#include <stdint.h>

// ---------------- problem constants ----------------
constexpr int B_  = 64;
constexpr int N_  = 257;
constexpr int C_  = 768;
constexpr int H_  = 12;
constexpr int D_  = 64;           // C_/H_
constexpr int HID_ = 3072;
constexpr int M_  = B_ * N_;      // 16448 rows
constexpr int C3_ = 3 * C_;       // 2304

constexpr size_t SZ_BNC  = (size_t)M_ * C_;
constexpr size_t SZ_QKV  = (size_t)M_ * C3_;
constexpr size_t SZ_ATT  = (size_t)B_ * H_ * N_ * N_;
constexpr size_t SZ_HID  = (size_t)M_ * HID_;
constexpr size_t SZ_ASUM = (size_t)B_ * N_ * N_;

// weight scratch offsets (elements)
constexpr size_t W_SQKV  = 0;
constexpr size_t W_CQKV  = W_SQKV + (size_t)C3_ * C_;
constexpr size_t W_SPROJ = W_CQKV + (size_t)C3_ * C_;
constexpr size_t W_CPROJ = W_SPROJ + (size_t)C_ * C_;
constexpr size_t W_FC1   = W_CPROJ + (size_t)C_ * C_;
constexpr size_t W_FC2   = W_FC1 + (size_t)HID_ * C_;
constexpr size_t W_TOTAL = W_FC2 + (size_t)C_ * HID_;

// ---------------- device scratch (static, no allocs) ----------------
__device__ float g_s   [SZ_BNC];
__device__ float g_t   [SZ_BNC];
__device__ float g_q1  [SZ_QKV];
__device__ float g_q2  [SZ_QKV];
__device__ float g_att [SZ_ATT];
__device__ float g_sc  [SZ_BNC];
__device__ float g_asum[SZ_ASUM];
__device__ float g_heat[(size_t)B_ * N_];
__device__ __nv_bfloat16 g_lnh[SZ_BNC];
__device__ __nv_bfloat16 g_lnl[SZ_BNC];
__device__ __nv_bfloat16 g_obh[SZ_BNC];
__device__ __nv_bfloat16 g_obl[SZ_BNC];
__device__ __nv_bfloat16 g_hdh[SZ_HID];
__device__ __nv_bfloat16 g_hdl[SZ_HID];
__device__ __nv_bfloat16 g_wh [W_TOTAL];
__device__ __nv_bfloat16 g_wl [W_TOTAL];

// ================= helpers =================
__device__ __forceinline__ uint32_t smem_u32(const void* p) {
    uint32_t a;
    asm("{ .reg .u64 t; cvta.to.shared.u64 t, %1; cvt.u32.u64 %0, t; }"
        : "=r"(a) : "l"(p));
    return a;
}

#define SW128(o) ((o) ^ (((o) >> 3) & 0x70))

#define LDSM_X4(r0, r1, r2, r3, addr) \
    asm volatile("ldmatrix.sync.aligned.m8n8.x4.shared.b16 {%0,%1,%2,%3}, [%4];" \
        : "=r"(r0), "=r"(r1), "=r"(r2), "=r"(r3) : "r"(addr))

#define LDSM_X2(r0, r1, addr) \
    asm volatile("ldmatrix.sync.aligned.m8n8.x2.shared.b16 {%0,%1}, [%2];" \
        : "=r"(r0), "=r"(r1) : "r"(addr))

#define MMA16816(d, a, b0, b1) \
    asm volatile("mma.sync.aligned.m16n8k16.row.col.f32.bf16.bf16.f32 " \
        "{%0,%1,%2,%3},{%4,%5,%6,%7},{%8,%9},{%0,%1,%2,%3};" \
        : "+f"((d)[0]), "+f"((d)[1]), "+f"((d)[2]), "+f"((d)[3]) \
        : "r"((a)[0]), "r"((a)[1]), "r"((a)[2]), "r"((a)[3]), "r"(b0), "r"(b1))

#define MMA_TF32(d, a, b0, b1) \
    asm volatile("mma.sync.aligned.m16n8k8.row.col.f32.tf32.tf32.f32 " \
        "{%0,%1,%2,%3},{%4,%5,%6,%7},{%8,%9},{%0,%1,%2,%3};" \
        : "+f"((d)[0]), "+f"((d)[1]), "+f"((d)[2]), "+f"((d)[3]) \
        : "r"((a)[0]), "r"((a)[1]), "r"((a)[2]), "r"((a)[3]), "r"(b0), "r"(b1))

// cp.async 16B with runtime src-size (0 => zero-fill)
#define CP_ASYNC16(dst, src, sz) \
    asm volatile("cp.async.cg.shared.global [%0], [%1], 16, %2;" \
        :: "r"(dst), "l"(src), "r"(sz))
#define CP_COMMIT() asm volatile("cp.async.commit_group;" ::: "memory")
#define CP_WAIT1()  asm volatile("cp.async.wait_group 1;" ::: "memory")
#define CP_WAIT0()  asm volatile("cp.async.wait_group 0;" ::: "memory")

__device__ __forceinline__ uint32_t f2tf(float f) {
    uint32_t r;
    asm("cvt.rna.tf32.f32 %0, %1;" : "=r"(r) : "f"(f));
    return r;
}

// hi/lo bf16 split of a float pair
__device__ __forceinline__ void hilo2(float a, float b, uint32_t& h, uint32_t& l) {
    __nv_bfloat162 h2 = __float22bfloat162_rn(make_float2(a, b));
    h = *(uint32_t*)&h2;
    float fa = __uint_as_float(h << 16);
    float fb = __uint_as_float(h & 0xFFFF0000u);
    __nv_bfloat162 l2 = __float22bfloat162_rn(make_float2(a - fa, b - fb));
    l = *(uint32_t*)&l2;
}

__device__ __forceinline__ float arf_f(float v) {
    float ep = expf(v), en = expf(-v), en4 = expf(-v - 4.0f);
    float tmp = (ep - en) / (ep + en4);
    return tmp < 0.0f ? 0.0f : tmp;
}

// ================= weight pre-conversion =================
__global__ void k_cvtw(const float* __restrict__ w, __nv_bfloat16* __restrict__ wh,
                       __nv_bfloat16* __restrict__ wl, size_t n) {
    size_t i0 = ((size_t)blockIdx.x * 256 + threadIdx.x) * 2;
    if (i0 >= n) return;
    uint32_t h, l;
    hilo2(w[i0], w[i0 + 1], h, l);
    *(uint32_t*)(wh + i0) = h;
    *(uint32_t*)(wl + i0) = l;
}

// ================= split-bf16 mma.sync GEMM (cp.async, 2 CTAs/SM) =================
// ACT: 0 none, 1 gelu(exact erf), 2 arf
// MODE: 0: C=v ; 1: C=v, C2=R+v ; 2: C=R+v      (used when OUTBF==0)
// OUTBF: 1 -> write hi/lo bf16 pair to Oh/Ol instead
constexpr uint32_t T_AH = 0;
constexpr uint32_t T_AL = 8192;
constexpr uint32_t T_BH = 16384;
constexpr uint32_t T_BL = 24576;
constexpr uint32_t STAGE = 32768;
constexpr int GEMM_SMEM = 65536;

template<int ACT, int MODE, int OUTBF>
__global__ __launch_bounds__(256, 2)
void gemm_mma(const __nv_bfloat16* __restrict__ Ah, const __nv_bfloat16* __restrict__ Al,
              const __nv_bfloat16* __restrict__ Wh, const __nv_bfloat16* __restrict__ Wl,
              const float* __restrict__ bias, float* __restrict__ Cmat,
              float* __restrict__ C2, const float* __restrict__ R,
              __nv_bfloat16* __restrict__ Oh, __nv_bfloat16* __restrict__ Ol,
              int M, int Nn, int K) {
    extern __shared__ __align__(1024) char smem[];
    const uint32_t sb = smem_u32(smem);
    const int tid  = threadIdx.x;
    const int wid  = tid >> 5;
    const int lane = tid & 31;
    const int bm   = blockIdx.y * 128;
    const int bn   = blockIdx.x * 128;
    const int wm   = (wid & 3) * 32;
    const int wn   = (wid >> 2) * 64;

    const int lr = tid >> 1;
    const int lk = (tid & 1) * 16;
    const bool aOk = (bm + lr) < M;
    const uint32_t aSz = aOk ? 16u : 0u;
    const __nv_bfloat16* Aph = Ah + (size_t)(aOk ? (bm + lr) : 0) * K + lk;
    const __nv_bfloat16* Apl = Al + (size_t)(aOk ? (bm + lr) : 0) * K + lk;
    const __nv_bfloat16* Wph = Wh + (size_t)(bn + lr) * K + lk;
    const __nv_bfloat16* Wpl = Wl + (size_t)(bn + lr) * K + lk;

    // smem dst offsets for this thread (two 16B chunks per tile)
    uint32_t dsw[2];
    {
        const uint32_t soff = lr * 64u;
#pragma unroll
        for (int u = 0; u < 2; ++u) {
            uint32_t off = soff + (uint32_t)(lk + u * 8) * 2u;
            dsw[u] = SW128(off);
        }
    }

    float acc[2][8][4];
#pragma unroll
    for (int i = 0; i < 2; i++)
#pragma unroll
        for (int j = 0; j < 8; j++)
#pragma unroll
            for (int r = 0; r < 4; r++) acc[i][j][r] = 0.f;

    // ---- prologue: async load stage 0 ----
#pragma unroll
    for (int u = 0; u < 2; ++u) {
        CP_ASYNC16(sb + T_AH + dsw[u], Aph + u * 8, aSz);
        CP_ASYNC16(sb + T_AL + dsw[u], Apl + u * 8, aSz);
        CP_ASYNC16(sb + T_BH + dsw[u], Wph + u * 8, 16u);
        CP_ASYNC16(sb + T_BL + dsw[u], Wpl + u * 8, 16u);
    }
    CP_COMMIT();

    const int nit = K >> 5;
    for (int it = 0; it < nit; ++it) {
        // issue prefetch for next stage
        if (it + 1 < nit) {
            const int k0 = (it + 1) << 5;
            const uint32_t base = sb + (uint32_t)((it + 1) & 1) * STAGE;
#pragma unroll
            for (int u = 0; u < 2; ++u) {
                CP_ASYNC16(base + T_AH + dsw[u], Aph + k0 + u * 8, aSz);
                CP_ASYNC16(base + T_AL + dsw[u], Apl + k0 + u * 8, aSz);
                CP_ASYNC16(base + T_BH + dsw[u], Wph + k0 + u * 8, 16u);
                CP_ASYNC16(base + T_BL + dsw[u], Wpl + k0 + u * 8, 16u);
            }
            CP_COMMIT();
            CP_WAIT1();     // current stage complete (1 group still in flight)
        } else {
            CP_WAIT0();
        }
        __syncthreads();

        const uint32_t stb = sb + (uint32_t)(it & 1) * STAGE;
#pragma unroll
        for (int ks = 0; ks < 2; ++ks) {
            const int kk = ks * 16;
            uint32_t ah[2][4], al[2][4];
#pragma unroll
            for (int mt = 0; mt < 2; ++mt) {
                uint32_t off = (uint32_t)(wm + mt * 16 + (lane & 15)) * 64u
                             + (uint32_t)(kk + (lane >> 4) * 8) * 2u;
                uint32_t sw = SW128(off);
                LDSM_X4(ah[mt][0], ah[mt][1], ah[mt][2], ah[mt][3], stb + T_AH + sw);
                LDSM_X4(al[mt][0], al[mt][1], al[mt][2], al[mt][3], stb + T_AL + sw);
            }
            uint32_t bh_[8][2], bl_[8][2];
#pragma unroll
            for (int nt = 0; nt < 8; ++nt) {
                const int l8 = lane & 15;
                uint32_t boff = (uint32_t)(wn + nt * 8 + (l8 & 7)) * 64u
                              + (uint32_t)(kk + ((l8 >> 3) & 1) * 8) * 2u;
                uint32_t bsw = SW128(boff);
                LDSM_X2(bh_[nt][0], bh_[nt][1], stb + T_BH + bsw);
                LDSM_X2(bl_[nt][0], bl_[nt][1], stb + T_BL + bsw);
            }
            // term-major order: consecutive MMAs hit different accumulators
#pragma unroll
            for (int nt = 0; nt < 8; ++nt) {
                MMA16816(acc[0][nt], ah[0], bh_[nt][0], bh_[nt][1]);
                MMA16816(acc[1][nt], ah[1], bh_[nt][0], bh_[nt][1]);
            }
#pragma unroll
            for (int nt = 0; nt < 8; ++nt) {
                MMA16816(acc[0][nt], ah[0], bl_[nt][0], bl_[nt][1]);
                MMA16816(acc[1][nt], ah[1], bl_[nt][0], bl_[nt][1]);
            }
#pragma unroll
            for (int nt = 0; nt < 8; ++nt) {
                MMA16816(acc[0][nt], al[0], bh_[nt][0], bh_[nt][1]);
                MMA16816(acc[1][nt], al[1], bh_[nt][0], bh_[nt][1]);
            }
        }
        __syncthreads();   // all reads of stage (it&1) done before it is refilled
    }

#pragma unroll
    for (int mt = 0; mt < 2; ++mt) {
#pragma unroll
        for (int half = 0; half < 2; ++half) {
            const int row = bm + wm + mt * 16 + (lane >> 2) + half * 8;
            if (row < M) {
#pragma unroll
                for (int nt = 0; nt < 8; ++nt) {
                    const int col = bn + wn + nt * 8 + (lane & 3) * 2;
                    float v0 = acc[mt][nt][half * 2 + 0];
                    float v1 = acc[mt][nt][half * 2 + 1];
                    if (bias) { v0 += bias[col]; v1 += bias[col + 1]; }
                    if (ACT == 1) {
                        v0 = 0.5f * v0 * (1.0f + erff(v0 * 0.70710678118654752f));
                        v1 = 0.5f * v1 * (1.0f + erff(v1 * 0.70710678118654752f));
                    } else if (ACT == 2) {
                        v0 = arf_f(v0);
                        v1 = arf_f(v1);
                    }
                    const size_t oidx = (size_t)row * Nn + col;
                    if (OUTBF) {
                        uint32_t h, l;
                        hilo2(v0, v1, h, l);
                        *(uint32_t*)(Oh + oidx) = h;
                        *(uint32_t*)(Ol + oidx) = l;
                    } else if (MODE == 0) {
                        *(float2*)&Cmat[oidx] = make_float2(v0, v1);
                    } else if (MODE == 1) {
                        float2 r = *(const float2*)&R[oidx];
                        *(float2*)&Cmat[oidx] = make_float2(v0, v1);
                        *(float2*)&C2[oidx]   = make_float2(r.x + v0, r.y + v1);
                    } else {
                        float2 r = *(const float2*)&R[oidx];
                        *(float2*)&Cmat[oidx] = make_float2(r.x + v0, r.y + v1);
                    }
                }
            }
        }
    }
}

// ================= fused flash attention (tf32 mma, 512 thr) =================
constexpr int FA_NK  = 264;
constexpr int FA_KST = 68;
constexpr int FA_SST = 268;
constexpr int FA_OFF_Q = 0;
constexpr int FA_OFF_K = 64 * FA_KST;
constexpr int FA_OFF_S = FA_OFF_K + FA_NK * FA_KST;
constexpr int FA_FLOATS = FA_OFF_S + 64 * FA_SST;
constexpr int FATT_SMEM = FA_FLOATS * 4;             // 157,824 B

template<int WRITE_P>
__global__ __launch_bounds__(512, 1)
void k_fattn(const float* __restrict__ qsrc, int qs,
             const float* __restrict__ kvsrc, int kvs, int koff, int voff,
             __nv_bfloat16* __restrict__ oh, __nv_bfloat16* __restrict__ ol,
             float* __restrict__ pout) {
    extern __shared__ __align__(16) float fs[];
    uint32_t* Qs = (uint32_t*)(fs + FA_OFF_Q);
    uint32_t* Ks = (uint32_t*)(fs + FA_OFF_K);
    float*    Ss = fs + FA_OFF_S;

    const int q0 = blockIdx.x * 64;
    const int bh = blockIdx.y;
    const int b = bh / H_, h = bh % H_;
    const int tid = threadIdx.x;
    const int wid = tid >> 5;
    const int lane = tid & 31;
    const int gid = lane >> 2;
    const int tig = lane & 3;
    const int wq = wid & 3;
    const int wk = wid >> 2;
    const int r0 = wq * 16;

    const float* Qg = qsrc + (size_t)b * N_ * qs + h * D_;
    const float* Kg = kvsrc + (size_t)b * N_ * kvs + koff + h * D_;
    const float* Vg = kvsrc + (size_t)b * N_ * kvs + voff + h * D_;

    for (int idx = tid; idx < 64 * 64; idx += 512) {
        int r = idx >> 6, d = idx & 63;
        int q = q0 + r;
        Qs[r * FA_KST + d] = (q < N_) ? f2tf(Qg[(size_t)q * qs + d]) : 0u;
    }
    for (int idx = tid; idx < FA_NK * 64; idx += 512) {
        int r = idx >> 6, d = idx & 63;
        Ks[r * FA_KST + d] = (r < N_) ? f2tf(Kg[(size_t)r * kvs + d]) : 0u;
    }
    __syncthreads();

    // ---- phase 1: S = 0.125 * Q K^T ----
    {
        uint32_t a[8][4];
#pragma unroll
        for (int ks = 0; ks < 8; ++ks) {
            a[ks][0] = Qs[(r0 + gid)     * FA_KST + ks * 8 + tig];
            a[ks][1] = Qs[(r0 + gid + 8) * FA_KST + ks * 8 + tig];
            a[ks][2] = Qs[(r0 + gid)     * FA_KST + ks * 8 + 4 + tig];
            a[ks][3] = Qs[(r0 + gid + 8) * FA_KST + ks * 8 + 4 + tig];
        }
        const int g0 = wk * 8;
        const int g1 = (wk == 3) ? 33 : g0 + 8;
        int g = g0;
        for (; g + 4 <= g1; g += 4) {
            float c[4][4];
#pragma unroll
            for (int j = 0; j < 4; ++j)
#pragma unroll
                for (int r = 0; r < 4; ++r) c[j][r] = 0.f;
#pragma unroll
            for (int ks = 0; ks < 8; ++ks) {
#pragma unroll
                for (int j = 0; j < 4; ++j) {
                    uint32_t b0 = Ks[((g + j) * 8 + gid) * FA_KST + ks * 8 + tig];
                    uint32_t b1 = Ks[((g + j) * 8 + gid) * FA_KST + ks * 8 + 4 + tig];
                    MMA_TF32(c[j], a[ks], b0, b1);
                }
            }
#pragma unroll
            for (int j = 0; j < 4; ++j) {
                Ss[(r0 + gid)     * FA_SST + (g + j) * 8 + tig * 2]     = c[j][0] * 0.125f;
                Ss[(r0 + gid)     * FA_SST + (g + j) * 8 + tig * 2 + 1] = c[j][1] * 0.125f;
                Ss[(r0 + gid + 8) * FA_SST + (g + j) * 8 + tig * 2]     = c[j][2] * 0.125f;
                Ss[(r0 + gid + 8) * FA_SST + (g + j) * 8 + tig * 2 + 1] = c[j][3] * 0.125f;
            }
        }
        for (; g < g1; ++g) {
            float c[4] = {0.f, 0.f, 0.f, 0.f};
#pragma unroll
            for (int ks = 0; ks < 8; ++ks) {
                uint32_t b0 = Ks[(g * 8 + gid) * FA_KST + ks * 8 + tig];
                uint32_t b1 = Ks[(g * 8 + gid) * FA_KST + ks * 8 + 4 + tig];
                MMA_TF32(c, a[ks], b0, b1);
            }
            Ss[(r0 + gid)     * FA_SST + g * 8 + tig * 2]     = c[0] * 0.125f;
            Ss[(r0 + gid)     * FA_SST + g * 8 + tig * 2 + 1] = c[1] * 0.125f;
            Ss[(r0 + gid + 8) * FA_SST + g * 8 + tig * 2]     = c[2] * 0.125f;
            Ss[(r0 + gid + 8) * FA_SST + g * 8 + tig * 2 + 1] = c[3] * 0.125f;
        }
    }
    __syncthreads();

    // ---- phase 2: softmax (4 rows per warp, 16 warps) ----
#pragma unroll 1
    for (int rr = 0; rr < 4; ++rr) {
        const int row = wid * 4 + rr;
        const int q = q0 + row;
        if (q >= N_) continue;
        float* Sr = Ss + (size_t)row * FA_SST;
        float m = -1e30f;
        for (int c = lane; c < N_; c += 32) m = fmaxf(m, Sr[c]);
#pragma unroll
        for (int off = 16; off > 0; off >>= 1)
            m = fmaxf(m, __shfl_xor_sync(0xFFFFFFFF, m, off));
        float sum = 0.f;
        for (int c = lane; c < N_; c += 32) {
            float e = expf(Sr[c] - m);
            Sr[c] = e;
            sum += e;
        }
#pragma unroll
        for (int off = 16; off > 0; off >>= 1)
            sum += __shfl_xor_sync(0xFFFFFFFF, sum, off);
        const float inv = 1.0f / sum;
        for (int c = lane; c < FA_NK; c += 32) {
            float p = (c < N_) ? Sr[c] * inv : 0.f;
            Sr[c] = p;
            if (WRITE_P && c < N_)
                pout[(size_t)bh * N_ * N_ + (size_t)q * N_ + c] = p;
        }
    }
    __syncthreads();

    // ---- phase 3: Vt load (tf32), O = P V (2-term split on P) ----
    uint32_t* Vt = Ks;
    for (int idx = tid; idx < FA_NK * 64; idx += 512) {
        int key = idx >> 6, d = idx & 63;
        Vt[d * FA_SST + key] = (key < N_) ? f2tf(Vg[(size_t)key * kvs + d]) : 0u;
    }
    __syncthreads();

    float oa[2][4];
#pragma unroll
    for (int nt = 0; nt < 2; ++nt)
#pragma unroll
        for (int r = 0; r < 4; ++r) oa[nt][r] = 0.f;

#pragma unroll 1
    for (int ks = 0; ks < 33; ++ks) {
        float p0 = Ss[(r0 + gid)     * FA_SST + ks * 8 + tig];
        float p1 = Ss[(r0 + gid + 8) * FA_SST + ks * 8 + tig];
        float p2 = Ss[(r0 + gid)     * FA_SST + ks * 8 + 4 + tig];
        float p3 = Ss[(r0 + gid + 8) * FA_SST + ks * 8 + 4 + tig];
        uint32_t ah[4], al[4];
        ah[0] = f2tf(p0); al[0] = __float_as_uint(p0 - __uint_as_float(ah[0]));
        ah[1] = f2tf(p1); al[1] = __float_as_uint(p1 - __uint_as_float(ah[1]));
        ah[2] = f2tf(p2); al[2] = __float_as_uint(p2 - __uint_as_float(ah[2]));
        ah[3] = f2tf(p3); al[3] = __float_as_uint(p3 - __uint_as_float(ah[3]));
        uint32_t vb[2][2];
#pragma unroll
        for (int nt = 0; nt < 2; ++nt) {
            vb[nt][0] = Vt[(wk * 16 + nt * 8 + gid) * FA_SST + ks * 8 + tig];
            vb[nt][1] = Vt[(wk * 16 + nt * 8 + gid) * FA_SST + ks * 8 + 4 + tig];
        }
#pragma unroll
        for (int nt = 0; nt < 2; ++nt) MMA_TF32(oa[nt], ah, vb[nt][0], vb[nt][1]);
#pragma unroll
        for (int nt = 0; nt < 2; ++nt) MMA_TF32(oa[nt], al, vb[nt][0], vb[nt][1]);
    }

    // ---- write O as bf16 hi/lo pairs ----
    {
        const int q_a = q0 + r0 + gid;
        const int q_b = q_a + 8;
#pragma unroll
        for (int nt = 0; nt < 2; ++nt) {
            const int col = h * D_ + wk * 16 + nt * 8 + tig * 2;
            if (q_a < N_) {
                uint32_t hh, ll;
                hilo2(oa[nt][0], oa[nt][1], hh, ll);
                const size_t oidx = ((size_t)(b * N_ + q_a)) * C_ + col;
                *(uint32_t*)(oh + oidx) = hh;
                *(uint32_t*)(ol + oidx) = ll;
            }
            if (q_b < N_) {
                uint32_t hh, ll;
                hilo2(oa[nt][2], oa[nt][3], hh, ll);
                const size_t oidx = ((size_t)(b * N_ + q_b)) * C_ + col;
                *(uint32_t*)(oh + oidx) = hh;
                *(uint32_t*)(ol + oidx) = ll;
            }
        }
    }
}

// ---------------- elementwise kernels ----------------
__global__ void k_init(const float* __restrict__ src, const float* __restrict__ tgt,
                       const float* __restrict__ pos, float* __restrict__ s,
                       float* __restrict__ t) {
    size_t i = (size_t)blockIdx.x * blockDim.x + threadIdx.x;
    if (i >= SZ_BNC) return;
    size_t nc = i % ((size_t)N_ * C_);
    s[i] = src[i] + pos[nc];
    t[i] = tgt[i];
}

// ---------------- layernorm -> bf16 hi/lo ----------------
__global__ void k_ln(const float* __restrict__ x, const float* __restrict__ g,
                     const float* __restrict__ b, __nv_bfloat16* __restrict__ yh,
                     __nv_bfloat16* __restrict__ yl) {
    int row = blockIdx.x;
    int tid = threadIdx.x;
    const float* xr = x + (size_t)row * C_;
    float s = 0.f, q = 0.f;
    for (int i = tid; i < C_; i += 256) { float v = xr[i]; s += v; q += v * v; }
    __shared__ float rs[256], rq[256];
    rs[tid] = s; rq[tid] = q; __syncthreads();
    for (int o = 128; o > 0; o >>= 1) {
        if (tid < o) { rs[tid] += rs[tid + o]; rq[tid] += rq[tid + o]; }
        __syncthreads();
    }
    float mean = rs[0] * (1.0f / C_);
    float var  = rq[0] * (1.0f / C_) - mean * mean;
    float inv  = rsqrtf(var + 1e-5f);
    __nv_bfloat16* yhr = yh + (size_t)row * C_;
    __nv_bfloat16* ylr = yl + (size_t)row * C_;
    for (int i0 = tid * 2; i0 < C_; i0 += 512) {
        float v0 = (xr[i0]     - mean) * inv * g[i0]     + b[i0];
        float v1 = (xr[i0 + 1] - mean) * inv * g[i0 + 1] + b[i0 + 1];
        uint32_t h, l;
        hilo2(v0, v1, h, l);
        *(uint32_t*)(yhr + i0) = h;
        *(uint32_t*)(ylr + i0) = l;
    }
}

// ---------------- head sum ----------------
__global__ void k_headsum(const float* __restrict__ attn, float* __restrict__ asum) {
    size_t idx = (size_t)blockIdx.x * 256 + threadIdx.x;
    if (idx >= SZ_ASUM) return;
    size_t b = idx / ((size_t)N_ * N_);
    size_t r = idx % ((size_t)N_ * N_);
    float s = 0.f;
    for (int h = 0; h < H_; h++) s += attn[((size_t)(b * H_ + h)) * N_ * N_ + r];
    asum[idx] = s;
}

// ---------------- heat ----------------
__global__ void k_heat(const float* __restrict__ asum, float* __restrict__ heat) {
    int idx = blockIdx.x * 256 + threadIdx.x;
    if (idx >= B_ * N_) return;
    int b = idx / N_, m = idx % N_;
    const float* p = asum + (size_t)b * N_ * N_ + m;
    float s = 0.f;
    for (int n = 0; n < N_; n++) s += p[(size_t)n * N_];
    heat[idx] = s * (1.0f / N_);
}

// ---------------- tgt output ----------------
__global__ void k_tgt_out(const float* __restrict__ t, const float* __restrict__ saw,
                          const float* __restrict__ heat, float* __restrict__ out) {
    size_t i = (size_t)blockIdx.x * 256 + threadIdx.x;
    if (i >= SZ_BNC) return;
    int row = (int)(i / C_);
    int c   = (int)(i % C_);
    float gate = 1.0f / (1.0f + expf(-heat[row]));
    float tv = t[i];
    out[i] = tv + tv * saw[c] * gate;
}

// ---------------- attm copy ----------------
__global__ void k_attm(const float* __restrict__ asum, float* __restrict__ out) {
    size_t idx = (size_t)blockIdx.x * 256 + threadIdx.x;
    size_t total = (size_t)B_ * 256 * 256;
    if (idx >= total) return;
    size_t b = idx / 65536;
    size_t r = idx % 65536;
    int i = (int)(r >> 8), j = (int)(r & 255);
    out[idx] = asum[(size_t)b * N_ * N_ + (size_t)(i + 1) * N_ + (j + 1)];
}

// ---------------- host orchestration ----------------
static inline dim3 tc_grid(int Nn) { return dim3(Nn / 128, (M_ + 127) / 128); }
static inline int cvtw_grid(size_t n) { return (int)((n / 2 + 255) / 256); }

extern "C" void kernel_launch(void* const* d_in, const int* in_sizes, int n_in,
                              void* d_out, int out_size) {
    const float* in_src   = (const float*)d_in[0];
    const float* in_tgt   = (const float*)d_in[1];
    const float* sattn_qkv_w  = (const float*)d_in[2];
    const float* sattn_proj_w = (const float*)d_in[3];
    const float* sattn_proj_b = (const float*)d_in[4];
    const float* cattn_qkv_w  = (const float*)d_in[5];
    const float* cattn_proj_w = (const float*)d_in[6];
    const float* cattn_proj_b = (const float*)d_in[7];
    const float* n1g = (const float*)d_in[8];
    const float* n1b = (const float*)d_in[9];
    const float* n2g = (const float*)d_in[10];
    const float* n2b = (const float*)d_in[11];
    const float* fc1_w = (const float*)d_in[12];
    const float* fc1_b = (const float*)d_in[13];
    const float* fc2_w = (const float*)d_in[14];
    const float* fc2_b = (const float*)d_in[15];
    const float* saw   = (const float*)d_in[16];
    const float* pos   = (const float*)d_in[17];

    float *s, *t, *q1, *q2, *at, *sc, *as_, *ht;
    __nv_bfloat16 *lnh, *lnl, *obh, *obl, *hdh, *hdl, *wh, *wl;
    cudaGetSymbolAddress((void**)&s,   g_s);
    cudaGetSymbolAddress((void**)&t,   g_t);
    cudaGetSymbolAddress((void**)&q1,  g_q1);
    cudaGetSymbolAddress((void**)&q2,  g_q2);
    cudaGetSymbolAddress((void**)&at,  g_att);
    cudaGetSymbolAddress((void**)&sc,  g_sc);
    cudaGetSymbolAddress((void**)&as_, g_asum);
    cudaGetSymbolAddress((void**)&ht,  g_heat);
    cudaGetSymbolAddress((void**)&lnh, g_lnh);
    cudaGetSymbolAddress((void**)&lnl, g_lnl);
    cudaGetSymbolAddress((void**)&obh, g_obh);
    cudaGetSymbolAddress((void**)&obl, g_obl);
    cudaGetSymbolAddress((void**)&hdh, g_hdh);
    cudaGetSymbolAddress((void**)&hdl, g_hdl);
    cudaGetSymbolAddress((void**)&wh,  g_wh);
    cudaGetSymbolAddress((void**)&wl,  g_wl);

    cudaFuncSetAttribute((const void*)gemm_mma<0, 0, 0>,
                         cudaFuncAttributeMaxDynamicSharedMemorySize, GEMM_SMEM);
    cudaFuncSetAttribute((const void*)gemm_mma<0, 1, 0>,
                         cudaFuncAttributeMaxDynamicSharedMemorySize, GEMM_SMEM);
    cudaFuncSetAttribute((const void*)gemm_mma<0, 2, 0>,
                         cudaFuncAttributeMaxDynamicSharedMemorySize, GEMM_SMEM);
    cudaFuncSetAttribute((const void*)gemm_mma<1, 0, 1>,
                         cudaFuncAttributeMaxDynamicSharedMemorySize, GEMM_SMEM);
    cudaFuncSetAttribute((const void*)gemm_mma<2, 1, 0>,
                         cudaFuncAttributeMaxDynamicSharedMemorySize, GEMM_SMEM);
    cudaFuncSetAttribute((const void*)k_fattn<0>,
                         cudaFuncAttributeMaxDynamicSharedMemorySize, FATT_SMEM);
    cudaFuncSetAttribute((const void*)k_fattn<1>,
                         cudaFuncAttributeMaxDynamicSharedMemorySize, FATT_SMEM);

    float* out_src  = (float*)d_out;
    float* out_tgt  = out_src + SZ_BNC;
    float* out_attm = out_tgt + SZ_BNC;

    const int EW = (int)((SZ_BNC + 255) / 256);
    dim3 fa_grid((N_ + 63) / 64, B_ * H_);

    // ---- weight pre-conversion ----
    k_cvtw<<<cvtw_grid((size_t)C3_ * C_), 256>>>(sattn_qkv_w, wh + W_SQKV, wl + W_SQKV,
                                                 (size_t)C3_ * C_);
    k_cvtw<<<cvtw_grid((size_t)C3_ * C_), 256>>>(cattn_qkv_w, wh + W_CQKV, wl + W_CQKV,
                                                 (size_t)C3_ * C_);
    k_cvtw<<<cvtw_grid((size_t)C_ * C_), 256>>>(sattn_proj_w, wh + W_SPROJ, wl + W_SPROJ,
                                                (size_t)C_ * C_);
    k_cvtw<<<cvtw_grid((size_t)C_ * C_), 256>>>(cattn_proj_w, wh + W_CPROJ, wl + W_CPROJ,
                                                (size_t)C_ * C_);
    k_cvtw<<<cvtw_grid((size_t)HID_ * C_), 256>>>(fc1_w, wh + W_FC1, wl + W_FC1,
                                                  (size_t)HID_ * C_);
    k_cvtw<<<cvtw_grid((size_t)C_ * HID_), 256>>>(fc2_w, wh + W_FC2, wl + W_FC2,
                                                  (size_t)C_ * HID_);

    // ---- src = src + pos; t = tgt ----
    k_init<<<EW, 256>>>(in_src, in_tgt, pos, s, t);

    // ---- self attention on src ----
    k_ln<<<M_, 256>>>(s, n1g, n1b, lnh, lnl);
    gemm_mma<0, 0, 0><<<tc_grid(C3_), 256, GEMM_SMEM>>>(lnh, lnl, wh + W_SQKV, wl + W_SQKV,
        nullptr, q1, nullptr, nullptr, nullptr, nullptr, M_, C3_, C_);
    k_fattn<0><<<fa_grid, 512, FATT_SMEM>>>(q1, C3_, q1, C3_, C_, 2 * C_, obh, obl, nullptr);
    gemm_mma<0, 1, 0><<<tc_grid(C_), 256, GEMM_SMEM>>>(obh, obl, wh + W_SPROJ, wl + W_SPROJ,
        sattn_proj_b, sc, s, s, nullptr, nullptr, M_, C_, C_);
    k_ln<<<M_, 256>>>(sc, n2g, n2b, lnh, lnl);
    gemm_mma<1, 0, 1><<<tc_grid(HID_), 256, GEMM_SMEM>>>(lnh, lnl, wh + W_FC1, wl + W_FC1,
        fc1_b, nullptr, nullptr, nullptr, hdh, hdl, M_, HID_, C_);
    gemm_mma<0, 2, 0><<<tc_grid(C_), 256, GEMM_SMEM>>>(hdh, hdl, wh + W_FC2, wl + W_FC2,
        fc2_b, s, nullptr, s, nullptr, nullptr, M_, C_, HID_);

    // ---- self attention on tgt ----
    k_ln<<<M_, 256>>>(t, n1g, n1b, lnh, lnl);
    gemm_mma<0, 0, 0><<<tc_grid(C3_), 256, GEMM_SMEM>>>(lnh, lnl, wh + W_SQKV, wl + W_SQKV,
        nullptr, q1, nullptr, nullptr, nullptr, nullptr, M_, C3_, C_);
    k_fattn<0><<<fa_grid, 512, FATT_SMEM>>>(q1, C3_, q1, C3_, C_, 2 * C_, obh, obl, nullptr);
    gemm_mma<0, 1, 0><<<tc_grid(C_), 256, GEMM_SMEM>>>(obh, obl, wh + W_SPROJ, wl + W_SPROJ,
        sattn_proj_b, sc, t, t, nullptr, nullptr, M_, C_, C_);
    k_ln<<<M_, 256>>>(sc, n2g, n2b, lnh, lnl);
    gemm_mma<1, 0, 1><<<tc_grid(HID_), 256, GEMM_SMEM>>>(lnh, lnl, wh + W_FC1, wl + W_FC1,
        fc1_b, nullptr, nullptr, nullptr, hdh, hdl, M_, HID_, C_);
    gemm_mma<0, 2, 0><<<tc_grid(C_), 256, GEMM_SMEM>>>(hdh, hdl, wh + W_FC2, wl + W_FC2,
        fc2_b, t, nullptr, t, nullptr, nullptr, M_, C_, HID_);

    // ---- cross attention (Q-only GEMM for src, KV-only for tgt) ----
    k_ln<<<M_, 256>>>(s, n1g, n1b, lnh, lnl);
    gemm_mma<0, 0, 0><<<tc_grid(C_), 256, GEMM_SMEM>>>(lnh, lnl, wh + W_CQKV, wl + W_CQKV,
        nullptr, q1, nullptr, nullptr, nullptr, nullptr, M_, C_, C_);
    k_ln<<<M_, 256>>>(t, n1g, n1b, lnh, lnl);
    gemm_mma<0, 0, 0><<<tc_grid(2 * C_), 256, GEMM_SMEM>>>(lnh, lnl,
        wh + W_CQKV + (size_t)C_ * C_, wl + W_CQKV + (size_t)C_ * C_,
        nullptr, q2, nullptr, nullptr, nullptr, nullptr, M_, 2 * C_, C_);
    k_fattn<1><<<fa_grid, 512, FATT_SMEM>>>(q1, C_, q2, 2 * C_, 0, C_, obh, obl, at);
    k_headsum<<<(int)((SZ_ASUM + 255) / 256), 256>>>(at, as_);
    gemm_mma<2, 1, 0><<<tc_grid(C_), 256, GEMM_SMEM>>>(obh, obl, wh + W_CPROJ, wl + W_CPROJ,
        cattn_proj_b, sc, s, s, nullptr, nullptr, M_, C_, C_);
    k_ln<<<M_, 256>>>(sc, n2g, n2b, lnh, lnl);
    gemm_mma<1, 0, 1><<<tc_grid(HID_), 256, GEMM_SMEM>>>(lnh, lnl, wh + W_FC1, wl + W_FC1,
        fc1_b, nullptr, nullptr, nullptr, hdh, hdl, M_, HID_, C_);
    gemm_mma<0, 2, 0><<<tc_grid(C_), 256, GEMM_SMEM>>>(hdh, hdl, wh + W_FC2, wl + W_FC2,
        fc2_b, out_src, nullptr, s, nullptr, nullptr, M_, C_, HID_);

    // ---- gate + tgt out ----
    k_heat<<<(B_ * N_ + 255) / 256, 256>>>(as_, ht);
    k_tgt_out<<<EW, 256>>>(t, saw, ht, out_tgt);

    // ---- attm out ----
    k_attm<<<(int)(((size_t)B_ * 256 * 256 + 255) / 256), 256>>>(as_, out_attm);
}

// round 17
// speedup vs baseline: 1.7530x; 1.0441x over previous
#include <cuda_runtime.h>
#include <cuda_bf16.h>
#include <math.h>
#include <stdint.h>

// ---------------- problem constants ----------------
constexpr int B_  = 64;
constexpr int N_  = 257;
constexpr int C_  = 768;
constexpr int H_  = 12;
constexpr int D_  = 64;           // C_/H_
constexpr int HID_ = 3072;
constexpr int M_  = B_ * N_;      // 16448 rows
constexpr int C3_ = 3 * C_;       // 2304

constexpr size_t SZ_BNC  = (size_t)M_ * C_;
constexpr size_t SZ_QKV  = (size_t)M_ * C3_;
constexpr size_t SZ_ATT  = (size_t)B_ * H_ * N_ * N_;
constexpr size_t SZ_HID  = (size_t)M_ * HID_;
constexpr size_t SZ_ASUM = (size_t)B_ * N_ * N_;

// weight scratch offsets (elements)
constexpr size_t W_SQKV  = 0;
constexpr size_t W_CQKV  = W_SQKV + (size_t)C3_ * C_;
constexpr size_t W_SPROJ = W_CQKV + (size_t)C3_ * C_;
constexpr size_t W_CPROJ = W_SPROJ + (size_t)C_ * C_;
constexpr size_t W_FC1   = W_CPROJ + (size_t)C_ * C_;
constexpr size_t W_FC2   = W_FC1 + (size_t)HID_ * C_;
constexpr size_t W_TOTAL = W_FC2 + (size_t)C_ * HID_;

// ---------------- device scratch (static, no allocs) ----------------
__device__ float g_st  [2 * SZ_BNC];   // src | tgt residual streams
__device__ float g_q1  [2 * SZ_QKV];
__device__ float g_q2  [SZ_QKV];
__device__ float g_att [SZ_ATT];
__device__ float g_sc  [2 * SZ_BNC];
__device__ float g_asum[SZ_ASUM];
__device__ float g_heat[(size_t)B_ * N_];
__device__ __nv_bfloat16 g_lnh[2 * SZ_BNC];
__device__ __nv_bfloat16 g_lnl[2 * SZ_BNC];
__device__ __nv_bfloat16 g_obh[2 * SZ_BNC];
__device__ __nv_bfloat16 g_obl[2 * SZ_BNC];
__device__ __nv_bfloat16 g_hdh[2 * SZ_HID];
__device__ __nv_bfloat16 g_hdl[2 * SZ_HID];
__device__ __nv_bfloat16 g_wh [W_TOTAL];
__device__ __nv_bfloat16 g_wl [W_TOTAL];

// ================= helpers =================
__device__ __forceinline__ uint32_t smem_u32(const void* p) {
    uint32_t a;
    asm("{ .reg .u64 t; cvta.to.shared.u64 t, %1; cvt.u32.u64 %0, t; }"
        : "=r"(a) : "l"(p));
    return a;
}

#define SW128(o) ((o) ^ (((o) >> 3) & 0x70))

#define LDSM_X4(r0, r1, r2, r3, addr) \
    asm volatile("ldmatrix.sync.aligned.m8n8.x4.shared.b16 {%0,%1,%2,%3}, [%4];" \
        : "=r"(r0), "=r"(r1), "=r"(r2), "=r"(r3) : "r"(addr))

#define LDSM_X2(r0, r1, addr) \
    asm volatile("ldmatrix.sync.aligned.m8n8.x2.shared.b16 {%0,%1}, [%2];" \
        : "=r"(r0), "=r"(r1) : "r"(addr))

#define MMA16816(d, a, b0, b1) \
    asm volatile("mma.sync.aligned.m16n8k16.row.col.f32.bf16.bf16.f32 " \
        "{%0,%1,%2,%3},{%4,%5,%6,%7},{%8,%9},{%0,%1,%2,%3};" \
        : "+f"((d)[0]), "+f"((d)[1]), "+f"((d)[2]), "+f"((d)[3]) \
        : "r"((a)[0]), "r"((a)[1]), "r"((a)[2]), "r"((a)[3]), "r"(b0), "r"(b1))

#define MMA_TF32(d, a, b0, b1) \
    asm volatile("mma.sync.aligned.m16n8k8.row.col.f32.tf32.tf32.f32 " \
        "{%0,%1,%2,%3},{%4,%5,%6,%7},{%8,%9},{%0,%1,%2,%3};" \
        : "+f"((d)[0]), "+f"((d)[1]), "+f"((d)[2]), "+f"((d)[3]) \
        : "r"((a)[0]), "r"((a)[1]), "r"((a)[2]), "r"((a)[3]), "r"(b0), "r"(b1))

// cp.async 16B with runtime src-size (0 => zero-fill)
#define CP_ASYNC16(dst, src, sz) \
    asm volatile("cp.async.cg.shared.global [%0], [%1], 16, %2;" \
        :: "r"(dst), "l"(src), "r"(sz))
#define CP_COMMIT() asm volatile("cp.async.commit_group;" ::: "memory")
#define CP_WAIT1()  asm volatile("cp.async.wait_group 1;" ::: "memory")
#define CP_WAIT0()  asm volatile("cp.async.wait_group 0;" ::: "memory")

__device__ __forceinline__ uint32_t f2tf(float f) {
    uint32_t r;
    asm("cvt.rna.tf32.f32 %0, %1;" : "=r"(r) : "f"(f));
    return r;
}

// hi/lo bf16 split of a float pair
__device__ __forceinline__ void hilo2(float a, float b, uint32_t& h, uint32_t& l) {
    __nv_bfloat162 h2 = __float22bfloat162_rn(make_float2(a, b));
    h = *(uint32_t*)&h2;
    float fa = __uint_as_float(h << 16);
    float fb = __uint_as_float(h & 0xFFFF0000u);
    __nv_bfloat162 l2 = __float22bfloat162_rn(make_float2(a - fa, b - fb));
    l = *(uint32_t*)&l2;
}

__device__ __forceinline__ float arf_f(float v) {
    float ep = expf(v), en = expf(-v), en4 = expf(-v - 4.0f);
    float tmp = (ep - en) / (ep + en4);
    return tmp < 0.0f ? 0.0f : tmp;
}

// ================= weight pre-conversion =================
__global__ void k_cvtw(const float* __restrict__ w, __nv_bfloat16* __restrict__ wh,
                       __nv_bfloat16* __restrict__ wl, size_t n) {
    size_t i0 = ((size_t)blockIdx.x * 256 + threadIdx.x) * 2;
    if (i0 >= n) return;
    uint32_t h, l;
    hilo2(w[i0], w[i0 + 1], h, l);
    *(uint32_t*)(wh + i0) = h;
    *(uint32_t*)(wl + i0) = l;
}

// ================= split-bf16 mma.sync GEMM (3-stage cp.async, 2 CTAs/SM) =================
// ACT: 0 none, 1 gelu(exact erf), 2 arf
// MODE: 0: C=v ; 1: C=v, C2=R+v ; 2: C=R+v      (used when OUTBF==0)
// OUTBF: 1 -> write hi/lo bf16 pair to Oh/Ol instead
constexpr uint32_t T_AH = 0;
constexpr uint32_t T_AL = 8192;
constexpr uint32_t T_BH = 16384;
constexpr uint32_t T_BL = 24576;
constexpr uint32_t STAGE = 32768;
constexpr int GEMM_SMEM = 98304;   // 3 stages

template<int ACT, int MODE, int OUTBF>
__global__ __launch_bounds__(256, 2)
void gemm_mma(const __nv_bfloat16* __restrict__ Ah, const __nv_bfloat16* __restrict__ Al,
              const __nv_bfloat16* __restrict__ Wh, const __nv_bfloat16* __restrict__ Wl,
              const float* __restrict__ bias, float* __restrict__ Cmat,
              float* __restrict__ C2, const float* __restrict__ R,
              __nv_bfloat16* __restrict__ Oh, __nv_bfloat16* __restrict__ Ol,
              int M, int Nn, int K) {
    extern __shared__ __align__(1024) char smem[];
    const uint32_t sb = smem_u32(smem);
    const int tid  = threadIdx.x;
    const int wid  = tid >> 5;
    const int lane = tid & 31;
    const int bm   = blockIdx.y * 128;
    const int bn   = blockIdx.x * 128;
    const int wm   = (wid & 3) * 32;
    const int wn   = (wid >> 2) * 64;

    const int lr = tid >> 1;
    const int lk = (tid & 1) * 16;
    const bool aOk = (bm + lr) < M;
    const uint32_t aSz = aOk ? 16u : 0u;
    const __nv_bfloat16* Aph = Ah + (size_t)(aOk ? (bm + lr) : 0) * K + lk;
    const __nv_bfloat16* Apl = Al + (size_t)(aOk ? (bm + lr) : 0) * K + lk;
    const __nv_bfloat16* Wph = Wh + (size_t)(bn + lr) * K + lk;
    const __nv_bfloat16* Wpl = Wl + (size_t)(bn + lr) * K + lk;

    uint32_t dsw[2];
    {
        const uint32_t soff = lr * 64u;
#pragma unroll
        for (int u = 0; u < 2; ++u) {
            uint32_t off = soff + (uint32_t)(lk + u * 8) * 2u;
            dsw[u] = SW128(off);
        }
    }

    float acc[2][8][4];
#pragma unroll
    for (int i = 0; i < 2; i++)
#pragma unroll
        for (int j = 0; j < 8; j++)
#pragma unroll
            for (int r = 0; r < 4; r++) acc[i][j][r] = 0.f;

    const int nit = K >> 5;

    // ---- prologue: async load stages 0 and 1 ----
#pragma unroll
    for (int st = 0; st < 2; ++st) {
        const uint32_t base = sb + (uint32_t)st * STAGE;
        const int k0 = st << 5;
#pragma unroll
        for (int u = 0; u < 2; ++u) {
            CP_ASYNC16(base + T_AH + dsw[u], Aph + k0 + u * 8, aSz);
            CP_ASYNC16(base + T_AL + dsw[u], Apl + k0 + u * 8, aSz);
            CP_ASYNC16(base + T_BH + dsw[u], Wph + k0 + u * 8, 16u);
            CP_ASYNC16(base + T_BL + dsw[u], Wpl + k0 + u * 8, 16u);
        }
        CP_COMMIT();
    }

    int stage = 0;   // stage index of iteration it (mod 3)
    for (int it = 0; it < nit; ++it) {
        if (it < nit - 1) CP_WAIT1(); else CP_WAIT0();
        __syncthreads();   // stage `it` visible; all reads of stage (it-1)%3 done

        // issue prefetch for stage it+2 (overwrites buffer (it-1)%3 — safe post-barrier)
        if (it + 2 < nit) {
            int pst = stage + 2; if (pst >= 3) pst -= 3;
            const uint32_t base = sb + (uint32_t)pst * STAGE;
            const int k0 = (it + 2) << 5;
#pragma unroll
            for (int u = 0; u < 2; ++u) {
                CP_ASYNC16(base + T_AH + dsw[u], Aph + k0 + u * 8, aSz);
                CP_ASYNC16(base + T_AL + dsw[u], Apl + k0 + u * 8, aSz);
                CP_ASYNC16(base + T_BH + dsw[u], Wph + k0 + u * 8, 16u);
                CP_ASYNC16(base + T_BL + dsw[u], Wpl + k0 + u * 8, 16u);
            }
            CP_COMMIT();
        }

        const uint32_t stb = sb + (uint32_t)stage * STAGE;
#pragma unroll
        for (int ks = 0; ks < 2; ++ks) {
            const int kk = ks * 16;
            uint32_t ah[2][4], al[2][4];
#pragma unroll
            for (int mt = 0; mt < 2; ++mt) {
                uint32_t off = (uint32_t)(wm + mt * 16 + (lane & 15)) * 64u
                             + (uint32_t)(kk + (lane >> 4) * 8) * 2u;
                uint32_t sw = SW128(off);
                LDSM_X4(ah[mt][0], ah[mt][1], ah[mt][2], ah[mt][3], stb + T_AH + sw);
                LDSM_X4(al[mt][0], al[mt][1], al[mt][2], al[mt][3], stb + T_AL + sw);
            }
            uint32_t bh_[8][2], bl_[8][2];
#pragma unroll
            for (int nt = 0; nt < 8; ++nt) {
                const int l8 = lane & 15;
                uint32_t boff = (uint32_t)(wn + nt * 8 + (l8 & 7)) * 64u
                              + (uint32_t)(kk + ((l8 >> 3) & 1) * 8) * 2u;
                uint32_t bsw = SW128(boff);
                LDSM_X2(bh_[nt][0], bh_[nt][1], stb + T_BH + bsw);
                LDSM_X2(bl_[nt][0], bl_[nt][1], stb + T_BL + bsw);
            }
#pragma unroll
            for (int nt = 0; nt < 8; ++nt) {
                MMA16816(acc[0][nt], ah[0], bh_[nt][0], bh_[nt][1]);
                MMA16816(acc[1][nt], ah[1], bh_[nt][0], bh_[nt][1]);
            }
#pragma unroll
            for (int nt = 0; nt < 8; ++nt) {
                MMA16816(acc[0][nt], ah[0], bl_[nt][0], bl_[nt][1]);
                MMA16816(acc[1][nt], ah[1], bl_[nt][0], bl_[nt][1]);
            }
#pragma unroll
            for (int nt = 0; nt < 8; ++nt) {
                MMA16816(acc[0][nt], al[0], bh_[nt][0], bh_[nt][1]);
                MMA16816(acc[1][nt], al[1], bh_[nt][0], bh_[nt][1]);
            }
        }
        if (++stage == 3) stage = 0;
    }

#pragma unroll
    for (int mt = 0; mt < 2; ++mt) {
#pragma unroll
        for (int half = 0; half < 2; ++half) {
            const int row = bm + wm + mt * 16 + (lane >> 2) + half * 8;
            if (row < M) {
#pragma unroll
                for (int nt = 0; nt < 8; ++nt) {
                    const int col = bn + wn + nt * 8 + (lane & 3) * 2;
                    float v0 = acc[mt][nt][half * 2 + 0];
                    float v1 = acc[mt][nt][half * 2 + 1];
                    if (bias) { v0 += bias[col]; v1 += bias[col + 1]; }
                    if (ACT == 1) {
                        v0 = 0.5f * v0 * (1.0f + erff(v0 * 0.70710678118654752f));
                        v1 = 0.5f * v1 * (1.0f + erff(v1 * 0.70710678118654752f));
                    } else if (ACT == 2) {
                        v0 = arf_f(v0);
                        v1 = arf_f(v1);
                    }
                    const size_t oidx = (size_t)row * Nn + col;
                    if (OUTBF) {
                        uint32_t h, l;
                        hilo2(v0, v1, h, l);
                        *(uint32_t*)(Oh + oidx) = h;
                        *(uint32_t*)(Ol + oidx) = l;
                    } else if (MODE == 0) {
                        *(float2*)&Cmat[oidx] = make_float2(v0, v1);
                    } else if (MODE == 1) {
                        float2 r = *(const float2*)&R[oidx];
                        *(float2*)&Cmat[oidx] = make_float2(v0, v1);
                        *(float2*)&C2[oidx]   = make_float2(r.x + v0, r.y + v1);
                    } else {
                        float2 r = *(const float2*)&R[oidx];
                        *(float2*)&Cmat[oidx] = make_float2(r.x + v0, r.y + v1);
                    }
                }
            }
        }
    }
}

// ================= fused flash attention (tf32 mma, 512 thr) =================
constexpr int FA_NK  = 264;
constexpr int FA_KST = 68;
constexpr int FA_SST = 268;
constexpr int FA_OFF_Q = 0;
constexpr int FA_OFF_K = 64 * FA_KST;
constexpr int FA_OFF_S = FA_OFF_K + FA_NK * FA_KST;
constexpr int FA_FLOATS = FA_OFF_S + 64 * FA_SST;
constexpr int FATT_SMEM = FA_FLOATS * 4;             // 157,824 B

template<int WRITE_P>
__global__ __launch_bounds__(512, 1)
void k_fattn(const float* __restrict__ qsrc, int qs,
             const float* __restrict__ kvsrc, int kvs, int koff, int voff,
             __nv_bfloat16* __restrict__ oh, __nv_bfloat16* __restrict__ ol,
             float* __restrict__ pout) {
    extern __shared__ __align__(16) float fs[];
    uint32_t* Qs = (uint32_t*)(fs + FA_OFF_Q);
    uint32_t* Ks = (uint32_t*)(fs + FA_OFF_K);
    float*    Ss = fs + FA_OFF_S;

    const int q0 = blockIdx.x * 64;
    const int bh = blockIdx.y;
    const int b = bh / H_, h = bh % H_;
    const int tid = threadIdx.x;
    const int wid = tid >> 5;
    const int lane = tid & 31;
    const int gid = lane >> 2;
    const int tig = lane & 3;
    const int wq = wid & 3;
    const int wk = wid >> 2;
    const int r0 = wq * 16;

    const float* Qg = qsrc + (size_t)b * N_ * qs + h * D_;
    const float* Kg = kvsrc + (size_t)b * N_ * kvs + koff + h * D_;
    const float* Vg = kvsrc + (size_t)b * N_ * kvs + voff + h * D_;

    for (int idx = tid; idx < 64 * 64; idx += 512) {
        int r = idx >> 6, d = idx & 63;
        int q = q0 + r;
        Qs[r * FA_KST + d] = (q < N_) ? f2tf(Qg[(size_t)q * qs + d]) : 0u;
    }
    for (int idx = tid; idx < FA_NK * 64; idx += 512) {
        int r = idx >> 6, d = idx & 63;
        Ks[r * FA_KST + d] = (r < N_) ? f2tf(Kg[(size_t)r * kvs + d]) : 0u;
    }
    __syncthreads();

    // ---- phase 1: S = 0.125 * Q K^T ----
    {
        uint32_t a[8][4];
#pragma unroll
        for (int ks = 0; ks < 8; ++ks) {
            a[ks][0] = Qs[(r0 + gid)     * FA_KST + ks * 8 + tig];
            a[ks][1] = Qs[(r0 + gid + 8) * FA_KST + ks * 8 + tig];
            a[ks][2] = Qs[(r0 + gid)     * FA_KST + ks * 8 + 4 + tig];
            a[ks][3] = Qs[(r0 + gid + 8) * FA_KST + ks * 8 + 4 + tig];
        }
        const int g0 = wk * 8;
        const int g1 = (wk == 3) ? 33 : g0 + 8;
        int g = g0;
        for (; g + 4 <= g1; g += 4) {
            float c[4][4];
#pragma unroll
            for (int j = 0; j < 4; ++j)
#pragma unroll
                for (int r = 0; r < 4; ++r) c[j][r] = 0.f;
#pragma unroll
            for (int ks = 0; ks < 8; ++ks) {
#pragma unroll
                for (int j = 0; j < 4; ++j) {
                    uint32_t b0 = Ks[((g + j) * 8 + gid) * FA_KST + ks * 8 + tig];
                    uint32_t b1 = Ks[((g + j) * 8 + gid) * FA_KST + ks * 8 + 4 + tig];
                    MMA_TF32(c[j], a[ks], b0, b1);
                }
            }
#pragma unroll
            for (int j = 0; j < 4; ++j) {
                Ss[(r0 + gid)     * FA_SST + (g + j) * 8 + tig * 2]     = c[j][0] * 0.125f;
                Ss[(r0 + gid)     * FA_SST + (g + j) * 8 + tig * 2 + 1] = c[j][1] * 0.125f;
                Ss[(r0 + gid + 8) * FA_SST + (g + j) * 8 + tig * 2]     = c[j][2] * 0.125f;
                Ss[(r0 + gid + 8) * FA_SST + (g + j) * 8 + tig * 2 + 1] = c[j][3] * 0.125f;
            }
        }
        for (; g < g1; ++g) {
            float c[4] = {0.f, 0.f, 0.f, 0.f};
#pragma unroll
            for (int ks = 0; ks < 8; ++ks) {
                uint32_t b0 = Ks[(g * 8 + gid) * FA_KST + ks * 8 + tig];
                uint32_t b1 = Ks[(g * 8 + gid) * FA_KST + ks * 8 + 4 + tig];
                MMA_TF32(c, a[ks], b0, b1);
            }
            Ss[(r0 + gid)     * FA_SST + g * 8 + tig * 2]     = c[0] * 0.125f;
            Ss[(r0 + gid)     * FA_SST + g * 8 + tig * 2 + 1] = c[1] * 0.125f;
            Ss[(r0 + gid + 8) * FA_SST + g * 8 + tig * 2]     = c[2] * 0.125f;
            Ss[(r0 + gid + 8) * FA_SST + g * 8 + tig * 2 + 1] = c[3] * 0.125f;
        }
    }
    __syncthreads();

    // ---- phase 2: softmax (4 rows per warp, 16 warps) ----
#pragma unroll 1
    for (int rr = 0; rr < 4; ++rr) {
        const int row = wid * 4 + rr;
        const int q = q0 + row;
        if (q >= N_) continue;
        float* Sr = Ss + (size_t)row * FA_SST;
        float m = -1e30f;
        for (int c = lane; c < N_; c += 32) m = fmaxf(m, Sr[c]);
#pragma unroll
        for (int off = 16; off > 0; off >>= 1)
            m = fmaxf(m, __shfl_xor_sync(0xFFFFFFFF, m, off));
        float sum = 0.f;
        for (int c = lane; c < N_; c += 32) {
            float e = expf(Sr[c] - m);
            Sr[c] = e;
            sum += e;
        }
#pragma unroll
        for (int off = 16; off > 0; off >>= 1)
            sum += __shfl_xor_sync(0xFFFFFFFF, sum, off);
        const float inv = 1.0f / sum;
        for (int c = lane; c < FA_NK; c += 32) {
            float p = (c < N_) ? Sr[c] * inv : 0.f;
            Sr[c] = p;
            if (WRITE_P && c < N_)
                pout[(size_t)bh * N_ * N_ + (size_t)q * N_ + c] = p;
        }
    }
    __syncthreads();

    // ---- phase 3: Vt load (tf32), O = P V (2-term split on P) ----
    uint32_t* Vt = Ks;
    for (int idx = tid; idx < FA_NK * 64; idx += 512) {
        int key = idx >> 6, d = idx & 63;
        Vt[d * FA_SST + key] = (key < N_) ? f2tf(Vg[(size_t)key * kvs + d]) : 0u;
    }
    __syncthreads();

    float oa[2][4];
#pragma unroll
    for (int nt = 0; nt < 2; ++nt)
#pragma unroll
        for (int r = 0; r < 4; ++r) oa[nt][r] = 0.f;

#pragma unroll 1
    for (int ks = 0; ks < 33; ++ks) {
        float p0 = Ss[(r0 + gid)     * FA_SST + ks * 8 + tig];
        float p1 = Ss[(r0 + gid + 8) * FA_SST + ks * 8 + tig];
        float p2 = Ss[(r0 + gid)     * FA_SST + ks * 8 + 4 + tig];
        float p3 = Ss[(r0 + gid + 8) * FA_SST + ks * 8 + 4 + tig];
        uint32_t ah[4], al[4];
        ah[0] = f2tf(p0); al[0] = __float_as_uint(p0 - __uint_as_float(ah[0]));
        ah[1] = f2tf(p1); al[1] = __float_as_uint(p1 - __uint_as_float(ah[1]));
        ah[2] = f2tf(p2); al[2] = __float_as_uint(p2 - __uint_as_float(ah[2]));
        ah[3] = f2tf(p3); al[3] = __float_as_uint(p3 - __uint_as_float(ah[3]));
        uint32_t vb[2][2];
#pragma unroll
        for (int nt = 0; nt < 2; ++nt) {
            vb[nt][0] = Vt[(wk * 16 + nt * 8 + gid) * FA_SST + ks * 8 + tig];
            vb[nt][1] = Vt[(wk * 16 + nt * 8 + gid) * FA_SST + ks * 8 + 4 + tig];
        }
#pragma unroll
        for (int nt = 0; nt < 2; ++nt) MMA_TF32(oa[nt], ah, vb[nt][0], vb[nt][1]);
#pragma unroll
        for (int nt = 0; nt < 2; ++nt) MMA_TF32(oa[nt], al, vb[nt][0], vb[nt][1]);
    }

    // ---- write O as bf16 hi/lo pairs ----
    {
        const int q_a = q0 + r0 + gid;
        const int q_b = q_a + 8;
#pragma unroll
        for (int nt = 0; nt < 2; ++nt) {
            const int col = h * D_ + wk * 16 + nt * 8 + tig * 2;
            if (q_a < N_) {
                uint32_t hh, ll;
                hilo2(oa[nt][0], oa[nt][1], hh, ll);
                const size_t oidx = ((size_t)(b * N_ + q_a)) * C_ + col;
                *(uint32_t*)(oh + oidx) = hh;
                *(uint32_t*)(ol + oidx) = ll;
            }
            if (q_b < N_) {
                uint32_t hh, ll;
                hilo2(oa[nt][2], oa[nt][3], hh, ll);
                const size_t oidx = ((size_t)(b * N_ + q_b)) * C_ + col;
                *(uint32_t*)(oh + oidx) = hh;
                *(uint32_t*)(ol + oidx) = ll;
            }
        }
    }
}

// ---------------- elementwise kernels ----------------
__global__ void k_init(const float* __restrict__ src, const float* __restrict__ tgt,
                       const float* __restrict__ pos, float* __restrict__ s,
                       float* __restrict__ t) {
    size_t i = (size_t)blockIdx.x * blockDim.x + threadIdx.x;
    if (i >= SZ_BNC) return;
    size_t nc = i % ((size_t)N_ * C_);
    s[i] = src[i] + pos[nc];
    t[i] = tgt[i];
}

// ---------------- layernorm -> bf16 hi/lo ----------------
__global__ void k_ln(const float* __restrict__ x, const float* __restrict__ g,
                     const float* __restrict__ b, __nv_bfloat16* __restrict__ yh,
                     __nv_bfloat16* __restrict__ yl) {
    int row = blockIdx.x;
    int tid = threadIdx.x;
    const float* xr = x + (size_t)row * C_;
    float s = 0.f, q = 0.f;
    for (int i = tid; i < C_; i += 256) { float v = xr[i]; s += v; q += v * v; }
    __shared__ float rs[256], rq[256];
    rs[tid] = s; rq[tid] = q; __syncthreads();
    for (int o = 128; o > 0; o >>= 1) {
        if (tid < o) { rs[tid] += rs[tid + o]; rq[tid] += rq[tid + o]; }
        __syncthreads();
    }
    float mean = rs[0] * (1.0f / C_);
    float var  = rq[0] * (1.0f / C_) - mean * mean;
    float inv  = rsqrtf(var + 1e-5f);
    __nv_bfloat16* yhr = yh + (size_t)row * C_;
    __nv_bfloat16* ylr = yl + (size_t)row * C_;
    for (int i0 = tid * 2; i0 < C_; i0 += 512) {
        float v0 = (xr[i0]     - mean) * inv * g[i0]     + b[i0];
        float v1 = (xr[i0 + 1] - mean) * inv * g[i0 + 1] + b[i0 + 1];
        uint32_t h, l;
        hilo2(v0, v1, h, l);
        *(uint32_t*)(yhr + i0) = h;
        *(uint32_t*)(ylr + i0) = l;
    }
}

// ---------------- head sum ----------------
__global__ void k_headsum(const float* __restrict__ attn, float* __restrict__ asum) {
    size_t idx = (size_t)blockIdx.x * 256 + threadIdx.x;
    if (idx >= SZ_ASUM) return;
    size_t b = idx / ((size_t)N_ * N_);
    size_t r = idx % ((size_t)N_ * N_);
    float s = 0.f;
    for (int h = 0; h < H_; h++) s += attn[((size_t)(b * H_ + h)) * N_ * N_ + r];
    asum[idx] = s;
}

// ---------------- heat ----------------
__global__ void k_heat(const float* __restrict__ asum, float* __restrict__ heat) {
    int idx = blockIdx.x * 256 + threadIdx.x;
    if (idx >= B_ * N_) return;
    int b = idx / N_, m = idx % N_;
    const float* p = asum + (size_t)b * N_ * N_ + m;
    float s = 0.f;
    for (int n = 0; n < N_; n++) s += p[(size_t)n * N_];
    heat[idx] = s * (1.0f / N_);
}

// ---------------- tgt output ----------------
__global__ void k_tgt_out(const float* __restrict__ t, const float* __restrict__ saw,
                          const float* __restrict__ heat, float* __restrict__ out) {
    size_t i = (size_t)blockIdx.x * 256 + threadIdx.x;
    if (i >= SZ_BNC) return;
    int row = (int)(i / C_);
    int c   = (int)(i % C_);
    float gate = 1.0f / (1.0f + expf(-heat[row]));
    float tv = t[i];
    out[i] = tv + tv * saw[c] * gate;
}

// ---------------- attm copy ----------------
__global__ void k_attm(const float* __restrict__ asum, float* __restrict__ out) {
    size_t idx = (size_t)blockIdx.x * 256 + threadIdx.x;
    size_t total = (size_t)B_ * 256 * 256;
    if (idx >= total) return;
    size_t b = idx / 65536;
    size_t r = idx % 65536;
    int i = (int)(r >> 8), j = (int)(r & 255);
    out[idx] = asum[(size_t)b * N_ * N_ + (size_t)(i + 1) * N_ + (j + 1)];
}

// ---------------- host orchestration ----------------
static inline dim3 tc_grid_m(int Nn, int M) { return dim3(Nn / 128, (M + 127) / 128); }
static inline int cvtw_grid(size_t n) { return (int)((n / 2 + 255) / 256); }

extern "C" void kernel_launch(void* const* d_in, const int* in_sizes, int n_in,
                              void* d_out, int out_size) {
    const float* in_src   = (const float*)d_in[0];
    const float* in_tgt   = (const float*)d_in[1];
    const float* sattn_qkv_w  = (const float*)d_in[2];
    const float* sattn_proj_w = (const float*)d_in[3];
    const float* sattn_proj_b = (const float*)d_in[4];
    const float* cattn_qkv_w  = (const float*)d_in[5];
    const float* cattn_proj_w = (const float*)d_in[6];
    const float* cattn_proj_b = (const float*)d_in[7];
    const float* n1g = (const float*)d_in[8];
    const float* n1b = (const float*)d_in[9];
    const float* n2g = (const float*)d_in[10];
    const float* n2b = (const float*)d_in[11];
    const float* fc1_w = (const float*)d_in[12];
    const float* fc1_b = (const float*)d_in[13];
    const float* fc2_w = (const float*)d_in[14];
    const float* fc2_b = (const float*)d_in[15];
    const float* saw   = (const float*)d_in[16];
    const float* pos   = (const float*)d_in[17];

    float *st, *q1, *q2, *at, *sc, *as_, *ht;
    __nv_bfloat16 *lnh, *lnl, *obh, *obl, *hdh, *hdl, *wh, *wl;
    cudaGetSymbolAddress((void**)&st,  g_st);
    cudaGetSymbolAddress((void**)&q1,  g_q1);
    cudaGetSymbolAddress((void**)&q2,  g_q2);
    cudaGetSymbolAddress((void**)&at,  g_att);
    cudaGetSymbolAddress((void**)&sc,  g_sc);
    cudaGetSymbolAddress((void**)&as_, g_asum);
    cudaGetSymbolAddress((void**)&ht,  g_heat);
    cudaGetSymbolAddress((void**)&lnh, g_lnh);
    cudaGetSymbolAddress((void**)&lnl, g_lnl);
    cudaGetSymbolAddress((void**)&obh, g_obh);
    cudaGetSymbolAddress((void**)&obl, g_obl);
    cudaGetSymbolAddress((void**)&hdh, g_hdh);
    cudaGetSymbolAddress((void**)&hdl, g_hdl);
    cudaGetSymbolAddress((void**)&wh,  g_wh);
    cudaGetSymbolAddress((void**)&wl,  g_wl);

    float* s = st;
    float* t = st + SZ_BNC;

    cudaFuncSetAttribute((const void*)gemm_mma<0, 0, 0>,
                         cudaFuncAttributeMaxDynamicSharedMemorySize, GEMM_SMEM);
    cudaFuncSetAttribute((const void*)gemm_mma<0, 1, 0>,
                         cudaFuncAttributeMaxDynamicSharedMemorySize, GEMM_SMEM);
    cudaFuncSetAttribute((const void*)gemm_mma<0, 2, 0>,
                         cudaFuncAttributeMaxDynamicSharedMemorySize, GEMM_SMEM);
    cudaFuncSetAttribute((const void*)gemm_mma<1, 0, 1>,
                         cudaFuncAttributeMaxDynamicSharedMemorySize, GEMM_SMEM);
    cudaFuncSetAttribute((const void*)gemm_mma<2, 1, 0>,
                         cudaFuncAttributeMaxDynamicSharedMemorySize, GEMM_SMEM);
    cudaFuncSetAttribute((const void*)k_fattn<0>,
                         cudaFuncAttributeMaxDynamicSharedMemorySize, FATT_SMEM);
    cudaFuncSetAttribute((const void*)k_fattn<1>,
                         cudaFuncAttributeMaxDynamicSharedMemorySize, FATT_SMEM);

    float* out_src  = (float*)d_out;
    float* out_tgt  = out_src + SZ_BNC;
    float* out_attm = out_tgt + SZ_BNC;

    const int EW = (int)((SZ_BNC + 255) / 256);
    const int M2 = 2 * M_;
    dim3 fa_grid((N_ + 63) / 64, B_ * H_);
    dim3 fa_grid2((N_ + 63) / 64, 2 * B_ * H_);

    // ---- weight pre-conversion ----
    k_cvtw<<<cvtw_grid((size_t)C3_ * C_), 256>>>(sattn_qkv_w, wh + W_SQKV, wl + W_SQKV,
                                                 (size_t)C3_ * C_);
    k_cvtw<<<cvtw_grid((size_t)C3_ * C_), 256>>>(cattn_qkv_w, wh + W_CQKV, wl + W_CQKV,
                                                 (size_t)C3_ * C_);
    k_cvtw<<<cvtw_grid((size_t)C_ * C_), 256>>>(sattn_proj_w, wh + W_SPROJ, wl + W_SPROJ,
                                                (size_t)C_ * C_);
    k_cvtw<<<cvtw_grid((size_t)C_ * C_), 256>>>(cattn_proj_w, wh + W_CPROJ, wl + W_CPROJ,
                                                (size_t)C_ * C_);
    k_cvtw<<<cvtw_grid((size_t)HID_ * C_), 256>>>(fc1_w, wh + W_FC1, wl + W_FC1,
                                                  (size_t)HID_ * C_);
    k_cvtw<<<cvtw_grid((size_t)C_ * HID_), 256>>>(fc2_w, wh + W_FC2, wl + W_FC2,
                                                  (size_t)C_ * HID_);

    // ---- src = src + pos; t = tgt ----
    k_init<<<EW, 256>>>(in_src, in_tgt, pos, s, t);

    // ======== merged self attention (src & tgt as one 2M-row batch) ========
    k_ln<<<M2, 256>>>(st, n1g, n1b, lnh, lnl);
    gemm_mma<0, 0, 0><<<tc_grid_m(C3_, M2), 256, GEMM_SMEM>>>(lnh, lnl,
        wh + W_SQKV, wl + W_SQKV, nullptr, q1, nullptr, nullptr, nullptr, nullptr,
        M2, C3_, C_);
    k_fattn<0><<<fa_grid2, 512, FATT_SMEM>>>(q1, C3_, q1, C3_, C_, 2 * C_, obh, obl, nullptr);
    gemm_mma<0, 1, 0><<<tc_grid_m(C_, M2), 256, GEMM_SMEM>>>(obh, obl,
        wh + W_SPROJ, wl + W_SPROJ, sattn_proj_b, sc, st, st, nullptr, nullptr,
        M2, C_, C_);
    k_ln<<<M2, 256>>>(sc, n2g, n2b, lnh, lnl);
    gemm_mma<1, 0, 1><<<tc_grid_m(HID_, M2), 256, GEMM_SMEM>>>(lnh, lnl,
        wh + W_FC1, wl + W_FC1, fc1_b, nullptr, nullptr, nullptr, hdh, hdl,
        M2, HID_, C_);
    gemm_mma<0, 2, 0><<<tc_grid_m(C_, M2), 256, GEMM_SMEM>>>(hdh, hdl,
        wh + W_FC2, wl + W_FC2, fc2_b, st, nullptr, st, nullptr, nullptr,
        M2, C_, HID_);

    // ======== cross attention (Q-only GEMM for src, KV-only for tgt) ========
    k_ln<<<M_, 256>>>(s, n1g, n1b, lnh, lnl);
    gemm_mma<0, 0, 0><<<tc_grid_m(C_, M_), 256, GEMM_SMEM>>>(lnh, lnl,
        wh + W_CQKV, wl + W_CQKV, nullptr, q1, nullptr, nullptr, nullptr, nullptr,
        M_, C_, C_);
    k_ln<<<M_, 256>>>(t, n1g, n1b, lnh, lnl);
    gemm_mma<0, 0, 0><<<tc_grid_m(2 * C_, M_), 256, GEMM_SMEM>>>(lnh, lnl,
        wh + W_CQKV + (size_t)C_ * C_, wl + W_CQKV + (size_t)C_ * C_,
        nullptr, q2, nullptr, nullptr, nullptr, nullptr, M_, 2 * C_, C_);
    k_fattn<1><<<fa_grid, 512, FATT_SMEM>>>(q1, C_, q2, 2 * C_, 0, C_, obh, obl, at);
    k_headsum<<<(int)((SZ_ASUM + 255) / 256), 256>>>(at, as_);
    gemm_mma<2, 1, 0><<<tc_grid_m(C_, M_), 256, GEMM_SMEM>>>(obh, obl,
        wh + W_CPROJ, wl + W_CPROJ, cattn_proj_b, sc, s, s, nullptr, nullptr,
        M_, C_, C_);
    k_ln<<<M_, 256>>>(sc, n2g, n2b, lnh, lnl);
    gemm_mma<1, 0, 1><<<tc_grid_m(HID_, M_), 256, GEMM_SMEM>>>(lnh, lnl,
        wh + W_FC1, wl + W_FC1, fc1_b, nullptr, nullptr, nullptr, hdh, hdl,
        M_, HID_, C_);
    gemm_mma<0, 2, 0><<<tc_grid_m(C_, M_), 256, GEMM_SMEM>>>(hdh, hdl,
        wh + W_FC2, wl + W_FC2, fc2_b, out_src, nullptr, s, nullptr, nullptr,
        M_, C_, HID_);

    // ---- gate + tgt out ----
    k_heat<<<(B_ * N_ + 255) / 256, 256>>>(as_, ht);
    k_tgt_out<<<EW, 256>>>(t, saw, ht, out_tgt);

    // ---- attm out ----
    k_attm<<<(int)(((size_t)B_ * 256 * 256 + 255) / 256), 256>>>(as_, out_attm);
}